// round 14
// baseline (speedup 1.0000x reference)
#include <cuda_runtime.h>
#include <cuda_fp16.h>
#include <cstdint>

// ---------------- problem constants ----------------
#define BQ 16
#define HQ 256
#define NLEAF 15625
#define NINT 3906
#define NROWS (BQ * NLEAF)
#define TMG 128
#define TNG 128
#define KC 64
#define NSTAGE 20
#define STAGE_BYTES 32768          // A 16K | B 16K
#define SMEM_BYTES (4096 + 3 * STAGE_BYTES)
#define STAGE32 20480              // A 4K | B 16K
#define SMEM32 (4096 + 3 * STAGE32)
#define STAGE64 24576              // A 8K | B 16K
#define SMEM64 (4096 + 3 * STAGE64)
#define LEAF_BLOCKS ((NROWS + 63) / 64)

// ---------------- static device scratch ----------------
__device__ __half g_fA[(size_t)NROWS * HQ];        // 128 MB
__device__ __half g_fB[BQ * 3125 * HQ];
__device__ __half g_WT[3 * HQ * 1280];             // [t][n][k] fp16
__device__ int g_perm[196608];                     // static-capacity segments
__device__ int g_cursor[18];                       // per (level,type) count

__constant__ int c_n[6]      = {1, 5, 25, 125, 625, 3125};
__constant__ int c_off[6]    = {0, 1, 6, 31, 156, 781};
__constant__ int c_cumM[7]   = {0, 16, 96, 496, 2496, 12496, 62496};
// static segment capacity per level (rows, multiple of 128) and perm base
__constant__ int c_cap[6]    = {128, 128, 512, 2048, 10112, 50048};
__constant__ int c_pb[6]     = {0, 384, 768, 2304, 8448, 38784};

// ---------------- helpers ----------------
__device__ __forceinline__ uint32_t smem_u32(const void* p) {
    uint32_t a;
    asm("{ .reg .u64 t; cvta.to.shared.u64 t, %1; cvt.u32.u64 %0, t; }" : "=r"(a) : "l"(p));
    return a;
}
#define SWZ(x) ((x) ^ (((x) >> 3) & 0x70))

#define CP16(d, s)  asm volatile("cp.async.cg.shared.global [%0], [%1], 16;" :: "r"(d), "l"(s) : "memory")
#define CP_COMMIT() asm volatile("cp.async.commit_group;" ::: "memory")
#define CP_WAIT2()  asm volatile("cp.async.wait_group 2;" ::: "memory")

__device__ __forceinline__ void ldm4(uint32_t addr, uint32_t* r) {
    asm volatile("ldmatrix.sync.aligned.m8n8.x4.shared.b16 {%0,%1,%2,%3}, [%4];"
                 : "=r"(r[0]), "=r"(r[1]), "=r"(r[2]), "=r"(r[3]) : "r"(addr));
}
__device__ __forceinline__ void mma16816(float* c, const uint32_t* a, const uint32_t* b) {
    asm volatile(
        "mma.sync.aligned.m16n8k16.row.col.f32.f16.f16.f32 "
        "{%0,%1,%2,%3}, {%4,%5,%6,%7}, {%8,%9}, {%0,%1,%2,%3};"
        : "+f"(c[0]), "+f"(c[1]), "+f"(c[2]), "+f"(c[3])
        : "r"(a[0]), "r"(a[1]), "r"(a[2]), "r"(a[3]), "r"(b[0]), "r"(b[1]));
}

// ---------------- prep kernels ----------------
__global__ void k_reset() {
    int i = threadIdx.x;
    if (i < 18) g_cursor[i] = 0;
}

__device__ __forceinline__ void decode_row(int r, int& l, int& pr, int& b, int& j) {
    l = 0;
    while (r >= c_cumM[l + 1]) l++;
    pr = r - c_cumM[l];
    int n = c_n[l];
    b = pr / n;
    j = pr - b * n;
}

__global__ void k_scatter(const int* __restrict__ nt) {
    __shared__ int sc[18], sbase[18];
    int tid = threadIdx.x;
    if (tid < 18) sc[tid] = 0;
    __syncthreads();
    int r = blockIdx.x * blockDim.x + tid;
    int lt = -1, lpos = 0, l = 0, pr = 0;
    if (r < 62496) {
        int b, j;
        decode_row(r, l, pr, b, j);
        int t = nt[b * NINT + c_off[l] + j];
        lt = l * 3 + t;
        lpos = atomicAdd(&sc[lt], 1);
    }
    __syncthreads();
    if (tid < 18 && sc[tid]) sbase[tid] = atomicAdd(&g_cursor[tid], sc[tid]);
    __syncthreads();
    if (lt >= 0) {
        int t = lt - l * 3;
        g_perm[c_pb[l] + t * c_cap[l] + sbase[lt] + lpos] = pr;
    }
}

// ---------------- leaf encoder + fused coalesced W_node transpose ----------------
__global__ __launch_bounds__(256) void k_leaf(
    const float* __restrict__ lbox, const float* __restrict__ lsem,
    const float* __restrict__ Wb, const float* __restrict__ bb,
    const float* __restrict__ Ws, const float* __restrict__ bs,
    const float* __restrict__ Wn) {
    __shared__ float sbox[64][4];
    __shared__ float ssem[64][16];
    __shared__ float tile[32][33];
    int tid = threadIdx.x;

    if (blockIdx.x >= LEAF_BLOCKS) {
        // W_node transpose block (coalesced, R13-proven math)
        int bid = blockIdx.x - LEAF_BLOCKS;      // 0..959
        int nb = bid & 7;
        int kb = (bid >> 3) % 40;
        int t  = bid / 320;
        int tx = tid & 31;
        int ty = tid >> 5;
#pragma unroll
        for (int s = 0; s < 4; s++) {
            int kk = ty + s * 8;
            tile[kk][tx] = Wn[((size_t)t * 1280 + kb * 32 + kk) * HQ + nb * 32 + tx];
        }
        __syncthreads();
#pragma unroll
        for (int s = 0; s < 4; s++) {
            int rr = ty + s * 8;
            g_WT[((size_t)t * HQ + nb * 32 + rr) * 1280 + kb * 32 + tx] =
                __float2half(tile[tx][rr]);
        }
        return;
    }

    long row0 = (long)blockIdx.x * 64;
    {
        long lim = (long)NROWS * 4;
        if (tid < 256) {
            long gi = row0 * 4 + tid;
            sbox[tid >> 2][tid & 3] = (gi < lim) ? lbox[gi] : 0.f;
        }
        long lim2 = (long)NROWS * 16;
#pragma unroll
        for (int i = tid; i < 1024; i += 256) {
            long gi = row0 * 16 + i;
            ssem[i >> 4][i & 15] = (gi < lim2) ? lsem[gi] : 0.f;
        }
    }
    __syncthreads();

    int colgrp = tid & 63;
    int rowgrp = tid >> 6;
    int c = colgrp * 4;

    float4 wb[4], ws[16];
#pragma unroll
    for (int q = 0; q < 4; q++)  wb[q] = *(const float4*)(Wb + q * HQ + c);
#pragma unroll
    for (int q = 0; q < 16; q++) ws[q] = *(const float4*)(Ws + q * HQ + c);
    float4 bbv = *(const float4*)(bb + c);
    float4 bsv = *(const float4*)(bs + c);

#pragma unroll 4
    for (int rr = 0; rr < 16; rr++) {
        int rl = rowgrp * 16 + rr;
        long row = row0 + rl;
        if (row >= NROWS) break;
        float acc[4] = {bbv.x, bbv.y, bbv.z, bbv.w};
#pragma unroll
        for (int q = 0; q < 4; q++) {
            float x = sbox[rl][q];
            acc[0] = fmaf(x, wb[q].x, acc[0]); acc[1] = fmaf(x, wb[q].y, acc[1]);
            acc[2] = fmaf(x, wb[q].z, acc[2]); acc[3] = fmaf(x, wb[q].w, acc[3]);
        }
        float acs[4] = {bsv.x, bsv.y, bsv.z, bsv.w};
#pragma unroll
        for (int q = 0; q < 16; q++) {
            float x = ssem[rl][q];
            acs[0] = fmaf(x, ws[q].x, acs[0]); acs[1] = fmaf(x, ws[q].y, acs[1]);
            acs[2] = fmaf(x, ws[q].z, acs[2]); acs[3] = fmaf(x, ws[q].w, acs[3]);
        }
        float v0 = fmaxf(acc[0], 0.f) + fmaxf(acs[0], 0.f);
        float v1 = fmaxf(acc[1], 0.f) + fmaxf(acs[1], 0.f);
        float v2 = fmaxf(acc[2], 0.f) + fmaxf(acs[2], 0.f);
        float v3 = fmaxf(acc[3], 0.f) + fmaxf(acs[3], 0.f);
        __half2 h0 = __floats2half2_rn(v0, v1);
        __half2 h1 = __floats2half2_rn(v2, v3);
        *(uint2*)(g_fA + row * HQ + c) =
            make_uint2(*(uint32_t*)&h0, *(uint32_t*)&h1);
    }
}

// ---------------- common GEMM pieces ----------------
__device__ __forceinline__ void load_stage(
    uint32_t base, int k0, int t, int n0, int tid,
    const __half* __restrict__ src, const int* __restrict__ s_ab) {
#pragma unroll
    for (int i = 0; i < 4; i++) {
        int it = tid + i * 256;
        int row = (it >> 3) & 127;
        int ch = it & 7;
        const __half* sp = src + (size_t)s_ab[row] + k0 + ch * 8;
        uint32_t off = (uint32_t)(row * 128 + ch * 16);
        CP16(base + SWZ(off), sp);
    }
    const __half* wh = g_WT + (size_t)t * HQ * 1280;
    uint32_t bbase = base + 16384;
#pragma unroll
    for (int i = 0; i < 4; i++) {
        int it = tid + i * 256;
        int row = (it >> 3) & 127;
        int ch = it & 7;
        const __half* sp = wh + (size_t)(n0 + row) * 1280 + k0 + ch * 8;
        uint32_t off = (uint32_t)(row * 128 + ch * 16);
        CP16(bbase + SWZ(off), sp);
    }
}

__device__ __forceinline__ void shared_setup(
    char* smem, int t, int n0, int tid,
    const float* __restrict__ Wb, const float* __restrict__ bb,
    const float* __restrict__ bn) {
    float* s_wbox  = (float*)(smem + 1024);
    float* s_bbox  = (float*)(smem + 3072);
    float* s_bnode = (float*)(smem + 3584);
    if (tid < 128) {
#pragma unroll
        for (int q = 0; q < 4; q++) s_wbox[q * 128 + tid] = Wb[q * HQ + n0 + tid];
        s_bbox[tid] = bb[n0 + tid];
        s_bnode[tid] = bn[t * HQ + n0 + tid];
    }
}

__device__ __forceinline__ void epilogue(
    char* smem, float (*acc)[4][4], int wm, int wn, int lid,
    int n, int off, int n0, const float* __restrict__ ibox, __half* __restrict__ dst) {
    int*   s_pr    = (int*)(smem);
    float* s_wbox  = (float*)(smem + 1024);
    float* s_bbox  = (float*)(smem + 3072);
    float* s_bnode = (float*)(smem + 3584);
    int lq = lid >> 2, lr = (lid & 3) * 2;
#pragma unroll
    for (int mt = 0; mt < 4; mt++) {
#pragma unroll
        for (int h2 = 0; h2 < 2; h2++) {
            int m = wm * 64 + mt * 16 + lq + h2 * 8;
            int pr = s_pr[m];
            if (pr < 0) continue;
            int b = pr / n, j = pr - b * n;
            float4 bx = *(const float4*)(ibox + ((size_t)b * NINT + off + j) * 4);
#pragma unroll
            for (int nt = 0; nt < 4; nt++) {
                int cl = wn * 32 + nt * 8 + lr;
                float o[2];
#pragma unroll
                for (int u = 0; u < 2; u++) {
                    float be = s_bbox[cl + u];
                    be = fmaf(bx.x, s_wbox[cl + u], be);
                    be = fmaf(bx.y, s_wbox[128 + cl + u], be);
                    be = fmaf(bx.z, s_wbox[256 + cl + u], be);
                    be = fmaf(bx.w, s_wbox[384 + cl + u], be);
                    float v = acc[mt][nt][h2 * 2 + u] + s_bnode[cl + u];
                    o[u] = fmaxf(v, 0.f) + fmaxf(be, 0.f);
                }
                __half2 hv = __floats2half2_rn(o[0], o[1]);
                *(uint32_t*)(dst + (size_t)pr * HQ + n0 + cl) = *(uint32_t*)&hv;
            }
        }
    }
}

// ---------------- TM=128 GEMM (level 5) ----------------
__global__ __launch_bounds__(256, 2) void k_tc(
    int srcA, int lvl, int n, int off,
    const float* __restrict__ ibox, const float* __restrict__ bn,
    const float* __restrict__ Wb, const float* __restrict__ bb) {
    extern __shared__ __align__(128) char smem[];
    uint32_t sb = smem_u32(smem);
    int tid = threadIdx.x, wid = tid >> 5, lid = tid & 31;
    int wm = wid & 1, wn = wid >> 1;

    int cap = c_cap[lvl];
    int m0 = blockIdx.y * TMG;
    int seg = m0 / cap;
    int local = m0 - seg * cap;
    int cnt = g_cursor[lvl * 3 + seg];
    if (local >= cnt) return;
    int t = seg;
    int n0 = blockIdx.x * TNG;
    int pbase = c_pb[lvl] + seg * cap + local;

    const __half* src = srcA ? g_fA : g_fB;
    __half* dst = srcA ? g_fB : g_fA;

    int* s_pr = (int*)(smem);
    int* s_ab = (int*)(smem + 512);
    if (tid < TMG) {
        int pr = (local + tid < cnt) ? g_perm[pbase + tid] : -1;
        s_pr[tid] = pr;
        s_ab[tid] = (pr < 0 ? 0 : pr) * 1280;
    }
    shared_setup(smem, t, n0, tid, Wb, bb, bn);
    __syncthreads();

    load_stage(sb + 4096, 0, t, n0, tid, src, s_ab);
    CP_COMMIT();
    load_stage(sb + 4096 + STAGE_BYTES, KC, t, n0, tid, src, s_ab);
    CP_COMMIT();

    float acc[4][4][4];
#pragma unroll
    for (int i = 0; i < 4; i++)
#pragma unroll
        for (int j = 0; j < 4; j++)
#pragma unroll
            for (int q = 0; q < 4; q++) acc[i][j][q] = 0.f;

    int a_lrow = lid & 15;
    int a_lcol = (lid >> 4) & 1;
    int b_nrow = (lid & 7) | ((lid >> 1) & 8);
    int b_kcol = (lid >> 3) & 1;

    int stg = 0;
    for (int s = 0; s < NSTAGE; s++) {
        if (s + 2 < NSTAGE) {
            int ns = stg + 2; if (ns >= 3) ns -= 3;
            load_stage(sb + 4096 + ns * STAGE_BYTES, (s + 2) * KC, t, n0, tid, src, s_ab);
        }
        CP_COMMIT();
        CP_WAIT2();
        __syncthreads();

        uint32_t base = sb + 4096 + stg * STAGE_BYTES;
#pragma unroll
        for (int ks = 0; ks < 4; ks++) {
            uint32_t ah[4][4], bh[4][2];
#pragma unroll
            for (int mt = 0; mt < 4; mt++) {
                uint32_t offA = (uint32_t)((wm * 64 + mt * 16 + a_lrow) * 128 + ks * 32 + a_lcol * 16);
                ldm4(base + SWZ(offA), ah[mt]);
            }
#pragma unroll
            for (int np = 0; np < 2; np++) {
                uint32_t offB = (uint32_t)((wn * 32 + np * 16 + b_nrow) * 128 + ks * 32 + b_kcol * 16);
                uint32_t r[4];
                ldm4(base + 16384 + SWZ(offB), r);
                bh[2 * np][0] = r[0]; bh[2 * np][1] = r[1];
                bh[2 * np + 1][0] = r[2]; bh[2 * np + 1][1] = r[3];
            }
#pragma unroll
            for (int mt = 0; mt < 4; mt++)
#pragma unroll
                for (int nt = 0; nt < 4; nt++)
                    mma16816(acc[mt][nt], ah[mt], bh[nt]);
        }
        __syncthreads();
        stg++; if (stg >= 3) stg = 0;
    }

    epilogue(smem, acc, wm, wn, lid, n, off, n0, ibox, dst);
}

// ---------------- TM=64 GEMM (level 4) ----------------
__device__ __forceinline__ void load_stage64(
    uint32_t base, int k0, int t, int n0, int tid,
    const __half* __restrict__ src, const int* __restrict__ s_ab) {
#pragma unroll
    for (int i = 0; i < 2; i++) {
        int it = tid + i * 256;
        int row = (it >> 3) & 63;
        int ch = it & 7;
        const __half* sp = src + (size_t)s_ab[row] + k0 + ch * 8;
        uint32_t off = (uint32_t)(row * 128 + ch * 16);
        CP16(base + SWZ(off), sp);
    }
    const __half* wh = g_WT + (size_t)t * HQ * 1280;
    uint32_t bbase = base + 8192;
#pragma unroll
    for (int i = 0; i < 4; i++) {
        int it = tid + i * 256;
        int row = (it >> 3) & 127;
        int ch = it & 7;
        const __half* sp = wh + (size_t)(n0 + row) * 1280 + k0 + ch * 8;
        uint32_t off = (uint32_t)(row * 128 + ch * 16);
        CP16(bbase + SWZ(off), sp);
    }
}

__global__ __launch_bounds__(256, 2) void k_tc64(
    int srcA, int lvl, int n, int off,
    const float* __restrict__ ibox, const float* __restrict__ bn,
    const float* __restrict__ Wb, const float* __restrict__ bb) {
    extern __shared__ __align__(128) char smem[];
    uint32_t sb = smem_u32(smem);
    int tid = threadIdx.x, wid = tid >> 5, lid = tid & 31;
    int wm = wid & 1, wn = wid >> 1;

    int cap = c_cap[lvl];
    int m0 = blockIdx.y * 64;
    int seg = m0 / cap;
    int local = m0 - seg * cap;
    int cnt = g_cursor[lvl * 3 + seg];
    if (local >= cnt) return;
    int t = seg;
    int n0 = blockIdx.x * TNG;
    int pbase = c_pb[lvl] + seg * cap + local;

    const __half* src = srcA ? g_fA : g_fB;
    __half* dst = srcA ? g_fB : g_fA;

    int* s_pr = (int*)(smem);
    int* s_ab = (int*)(smem + 512);
    if (tid < 64) {
        int pr = (local + tid < cnt) ? g_perm[pbase + tid] : -1;
        s_pr[tid] = pr;
        s_ab[tid] = (pr < 0 ? 0 : pr) * 1280;
    }
    shared_setup(smem, t, n0, tid, Wb, bb, bn);
    __syncthreads();

    load_stage64(sb + 4096, 0, t, n0, tid, src, s_ab);
    CP_COMMIT();
    load_stage64(sb + 4096 + STAGE64, KC, t, n0, tid, src, s_ab);
    CP_COMMIT();

    float acc[2][4][4];
#pragma unroll
    for (int i = 0; i < 2; i++)
#pragma unroll
        for (int j = 0; j < 4; j++)
#pragma unroll
            for (int q = 0; q < 4; q++) acc[i][j][q] = 0.f;

    int a_lrow = lid & 15;
    int a_lcol = (lid >> 4) & 1;
    int b_nrow = (lid & 7) | ((lid >> 1) & 8);
    int b_kcol = (lid >> 3) & 1;

    int stg = 0;
    for (int s = 0; s < NSTAGE; s++) {
        if (s + 2 < NSTAGE) {
            int ns = stg + 2; if (ns >= 3) ns -= 3;
            load_stage64(sb + 4096 + ns * STAGE64, (s + 2) * KC, t, n0, tid, src, s_ab);
        }
        CP_COMMIT();
        CP_WAIT2();
        __syncthreads();

        uint32_t base = sb + 4096 + stg * STAGE64;
#pragma unroll
        for (int ks = 0; ks < 4; ks++) {
            uint32_t ah[2][4], bh[4][2];
#pragma unroll
            for (int mt = 0; mt < 2; mt++) {
                uint32_t offA = (uint32_t)((wm * 32 + mt * 16 + a_lrow) * 128 + ks * 32 + a_lcol * 16);
                ldm4(base + SWZ(offA), ah[mt]);
            }
#pragma unroll
            for (int np = 0; np < 2; np++) {
                uint32_t offB = (uint32_t)((wn * 32 + np * 16 + b_nrow) * 128 + ks * 32 + b_kcol * 16);
                uint32_t r[4];
                ldm4(base + 8192 + SWZ(offB), r);
                bh[2 * np][0] = r[0]; bh[2 * np][1] = r[1];
                bh[2 * np + 1][0] = r[2]; bh[2 * np + 1][1] = r[3];
            }
#pragma unroll
            for (int mt = 0; mt < 2; mt++)
#pragma unroll
                for (int nt = 0; nt < 4; nt++)
                    mma16816(acc[mt][nt], ah[mt], bh[nt]);
        }
        __syncthreads();
        stg++; if (stg >= 3) stg = 0;
    }

    int lq = lid >> 2, lr = (lid & 3) * 2;
#pragma unroll
    for (int mt = 0; mt < 2; mt++) {
#pragma unroll
        for (int h2 = 0; h2 < 2; h2++) {
            int m = wm * 32 + mt * 16 + lq + h2 * 8;
            int pr = ((int*)smem)[m];
            if (pr < 0) continue;
            int b = pr / n, j = pr - b * n;
            float4 bx = *(const float4*)(ibox + ((size_t)b * NINT + off + j) * 4);
            float* s_wbox  = (float*)(smem + 1024);
            float* s_bbox  = (float*)(smem + 3072);
            float* s_bnode = (float*)(smem + 3584);
#pragma unroll
            for (int nt = 0; nt < 4; nt++) {
                int cl = wn * 32 + nt * 8 + lr;
                float o[2];
#pragma unroll
                for (int u = 0; u < 2; u++) {
                    float be = s_bbox[cl + u];
                    be = fmaf(bx.x, s_wbox[cl + u], be);
                    be = fmaf(bx.y, s_wbox[128 + cl + u], be);
                    be = fmaf(bx.z, s_wbox[256 + cl + u], be);
                    be = fmaf(bx.w, s_wbox[384 + cl + u], be);
                    float v = acc[mt][nt][h2 * 2 + u] + s_bnode[cl + u];
                    o[u] = fmaxf(v, 0.f) + fmaxf(be, 0.f);
                }
                __half2 hv = __floats2half2_rn(o[0], o[1]);
                *(uint32_t*)(dst + (size_t)pr * HQ + n0 + cl) = *(uint32_t*)&hv;
            }
        }
    }
}

// ---------------- TM=32 GEMM (levels 3..0) ----------------
__device__ __forceinline__ void load_stage32(
    uint32_t base, int k0, int t, int n0, int tid,
    const __half* __restrict__ src, const int* __restrict__ s_ab) {
    {
        int row = (tid >> 3) & 31;
        int ch = tid & 7;
        const __half* sp = src + (size_t)s_ab[row] + k0 + ch * 8;
        uint32_t off = (uint32_t)(row * 128 + ch * 16);
        CP16(base + SWZ(off), sp);
    }
    const __half* wh = g_WT + (size_t)t * HQ * 1280;
    uint32_t bbase = base + 4096;
#pragma unroll
    for (int i = 0; i < 4; i++) {
        int it = tid + i * 256;
        int row = (it >> 3) & 127;
        int ch = it & 7;
        const __half* sp = wh + (size_t)(n0 + row) * 1280 + k0 + ch * 8;
        uint32_t off = (uint32_t)(row * 128 + ch * 16);
        CP16(bbase + SWZ(off), sp);
    }
}

__global__ __launch_bounds__(256, 2) void k_tc32(
    int srcA, int lvl, int n, int off,
    const float* __restrict__ ibox, const float* __restrict__ bn,
    const float* __restrict__ Wb, const float* __restrict__ bb) {
    extern __shared__ __align__(128) char smem[];
    uint32_t sb = smem_u32(smem);
    int tid = threadIdx.x, wid = tid >> 5, lid = tid & 31;
    int wn = wid;

    int cap = c_cap[lvl];
    int m0 = blockIdx.y * 32;
    int seg = m0 / cap;
    int local = m0 - seg * cap;
    int cnt = g_cursor[lvl * 3 + seg];
    if (local >= cnt) return;
    int t = seg;
    int n0 = blockIdx.x * TNG;
    int pbase = c_pb[lvl] + seg * cap + local;

    const __half* src = srcA ? g_fA : g_fB;
    __half* dst = srcA ? g_fB : g_fA;

    int* s_pr = (int*)(smem);
    int* s_ab = (int*)(smem + 512);
    if (tid < 32) {
        int pr = (local + tid < cnt) ? g_perm[pbase + tid] : -1;
        s_pr[tid] = pr;
        s_ab[tid] = (pr < 0 ? 0 : pr) * 1280;
    }
    shared_setup(smem, t, n0, tid, Wb, bb, bn);
    __syncthreads();

    load_stage32(sb + 4096, 0, t, n0, tid, src, s_ab);
    CP_COMMIT();
    load_stage32(sb + 4096 + STAGE32, KC, t, n0, tid, src, s_ab);
    CP_COMMIT();

    float acc[2][2][4];
#pragma unroll
    for (int i = 0; i < 2; i++)
#pragma unroll
        for (int j = 0; j < 2; j++)
#pragma unroll
            for (int q = 0; q < 4; q++) acc[i][j][q] = 0.f;

    int a_lrow = lid & 15;
    int a_lcol = (lid >> 4) & 1;
    int b_nrow = (lid & 7) | ((lid >> 1) & 8);
    int b_kcol = (lid >> 3) & 1;

    int stg = 0;
    for (int s = 0; s < NSTAGE; s++) {
        if (s + 2 < NSTAGE) {
            int ns = stg + 2; if (ns >= 3) ns -= 3;
            load_stage32(sb + 4096 + ns * STAGE32, (s + 2) * KC, t, n0, tid, src, s_ab);
        }
        CP_COMMIT();
        CP_WAIT2();
        __syncthreads();

        uint32_t base = sb + 4096 + stg * STAGE32;
#pragma unroll
        for (int ks = 0; ks < 4; ks++) {
            uint32_t ah[2][4], bh[2][2];
#pragma unroll
            for (int mt = 0; mt < 2; mt++) {
                uint32_t offA = (uint32_t)((mt * 16 + a_lrow) * 128 + ks * 32 + a_lcol * 16);
                ldm4(base + SWZ(offA), ah[mt]);
            }
            {
                uint32_t offB = (uint32_t)((wn * 16 + b_nrow) * 128 + ks * 32 + b_kcol * 16);
                uint32_t r[4];
                ldm4(base + 4096 + SWZ(offB), r);
                bh[0][0] = r[0]; bh[0][1] = r[1];
                bh[1][0] = r[2]; bh[1][1] = r[3];
            }
#pragma unroll
            for (int mt = 0; mt < 2; mt++)
#pragma unroll
                for (int nt = 0; nt < 2; nt++)
                    mma16816(acc[mt][nt], ah[mt], bh[nt]);
        }
        __syncthreads();
        stg++; if (stg >= 3) stg = 0;
    }

    int lq = lid >> 2, lr = (lid & 3) * 2;
    float* s_wbox  = (float*)(smem + 1024);
    float* s_bbox  = (float*)(smem + 3072);
    float* s_bnode = (float*)(smem + 3584);
#pragma unroll
    for (int mt = 0; mt < 2; mt++) {
#pragma unroll
        for (int h2 = 0; h2 < 2; h2++) {
            int m = mt * 16 + lq + h2 * 8;
            int pr = s_pr[m];
            if (pr < 0) continue;
            int b = pr / n, j = pr - b * n;
            float4 bx = *(const float4*)(ibox + ((size_t)b * NINT + off + j) * 4);
#pragma unroll
            for (int nt = 0; nt < 2; nt++) {
                int cl = wn * 16 + nt * 8 + lr;
                float o[2];
#pragma unroll
                for (int u = 0; u < 2; u++) {
                    float be = s_bbox[cl + u];
                    be = fmaf(bx.x, s_wbox[cl + u], be);
                    be = fmaf(bx.y, s_wbox[128 + cl + u], be);
                    be = fmaf(bx.z, s_wbox[256 + cl + u], be);
                    be = fmaf(bx.w, s_wbox[384 + cl + u], be);
                    float v = acc[mt][nt][h2 * 2 + u] + s_bnode[cl + u];
                    o[u] = fmaxf(v, 0.f) + fmaxf(be, 0.f);
                }
                __half2 hv = __floats2half2_rn(o[0], o[1]);
                *(uint32_t*)(dst + (size_t)pr * HQ + n0 + cl) = *(uint32_t*)&hv;
            }
        }
    }
}

// ---------------- VAE head ----------------
__global__ void k_head(const float* __restrict__ eps,
                       const float* __restrict__ W1, const float* __restrict__ b1,
                       const float* __restrict__ Wmu, const float* __restrict__ bmu,
                       const float* __restrict__ Wvar, const float* __restrict__ bvar,
                       float* __restrict__ out) {
    int b = blockIdx.x;
    int h = threadIdx.x;
    __shared__ float sroot[HQ];
    __shared__ float senc[HQ];
    sroot[h] = __half2float(g_fA[b * HQ + h]);
    __syncthreads();
    float a = b1[h];
    for (int k = 0; k < HQ; k++) a = fmaf(sroot[k], W1[k * HQ + h], a);
    senc[h] = fmaxf(a, 0.f);
    __syncthreads();
    float mu = bmu[h], lv = bvar[h];
    for (int k = 0; k < HQ; k++) {
        float e = senc[k];
        mu = fmaf(e, Wmu[k * HQ + h], mu);
        lv = fmaf(e, Wvar[k * HQ + h], lv);
    }
    float stdv = expf(0.5f * lv);
    out[b * 2 * HQ + h] = eps[b * HQ + h] * stdv + mu;
    out[b * 2 * HQ + HQ + h] = 1.f + lv - mu * mu - expf(lv);
}

// ---------------- launch ----------------
extern "C" void kernel_launch(void* const* d_in, const int* in_sizes, int n_in,
                              void* d_out, int out_size) {
    const float* leaf_box     = (const float*)d_in[0];
    const float* leaf_sem     = (const float*)d_in[1];
    const float* internal_box = (const float*)d_in[2];
    const int*   node_type    = (const int*)d_in[3];
    const float* eps          = (const float*)d_in[4];
    const float* W_box        = (const float*)d_in[5];
    const float* b_box        = (const float*)d_in[6];
    const float* W_sem        = (const float*)d_in[7];
    const float* b_sem        = (const float*)d_in[8];
    const float* W_node       = (const float*)d_in[9];
    const float* b_node       = (const float*)d_in[10];
    const float* W1           = (const float*)d_in[11];
    const float* b1           = (const float*)d_in[12];
    const float* Wmu          = (const float*)d_in[13];
    const float* bmu          = (const float*)d_in[14];
    const float* Wvar         = (const float*)d_in[15];
    const float* bvar         = (const float*)d_in[16];
    float* out = (float*)d_out;

    cudaFuncSetAttribute(k_tc, cudaFuncAttributeMaxDynamicSharedMemorySize, SMEM_BYTES);
    cudaFuncSetAttribute(k_tc64, cudaFuncAttributeMaxDynamicSharedMemorySize, SMEM64);
    cudaFuncSetAttribute(k_tc32, cudaFuncAttributeMaxDynamicSharedMemorySize, SMEM32);

    k_reset<<<1, 32>>>();
    k_scatter<<<(62496 + 255) / 256, 256>>>(node_type);
    k_leaf<<<LEAF_BLOCKS + 960, 256>>>(leaf_box, leaf_sem, W_box, b_box, W_sem, b_sem, W_node);

    // level 5: TM=128, grid covers 3 static segments of cap 50048
    {
        dim3 g5(2, 3 * (50048 / TMG));
        k_tc<<<g5, 256, SMEM_BYTES>>>(1, 5, 3125, 781, internal_box, b_node, W_box, b_box);
    }
    // level 4: TM=64, 3 segments of cap 10112
    {
        dim3 g4(2, 3 * (10112 / 64));
        k_tc64<<<g4, 256, SMEM64>>>(0, 4, 625, 156, internal_box, b_node, W_box, b_box);
    }
    // levels 3..0: TM=32
    struct Lv { int srcA, lvl, n, off, gy; };
    const Lv lv[4] = {
        {1, 3, 125, 31, 3 * (2048 / 32)},
        {0, 2,  25,  6, 3 * (512 / 32)},
        {1, 1,   5,  1, 3 * (128 / 32)},
        {0, 0,   1,  0, 3 * (128 / 32)},
    };
    for (int i = 0; i < 4; i++) {
        dim3 grid(2, lv[i].gy);
        k_tc32<<<grid, 256, SMEM32>>>(lv[i].srcA, lv[i].lvl, lv[i].n, lv[i].off,
                                      internal_box, b_node, W_box, b_box);
    }

    k_head<<<BQ, HQ>>>(eps, W1, b1, Wmu, bmu, Wvar, bvar, out);
}

// round 15
// speedup vs baseline: 1.0282x; 1.0282x over previous
#include <cuda_runtime.h>
#include <cuda_fp16.h>
#include <cstdint>

// ---------------- problem constants ----------------
#define BQ 16
#define HQ 256
#define NLEAF 15625
#define NINT 3906
#define NROWS (BQ * NLEAF)
#define TMG 128
#define TNG 128
#define KC 64
#define NSTAGE 20
#define STAGE32 20480              // A 4K | B 16K
#define SMEM32 (4096 + 3 * STAGE32)
#define STAGE64 24576              // A 8K | B 16K
#define SMEM64B (4096 + 2 * STAGE64)   // 2-stage ring, 3 CTA/SM

// ---------------- static device scratch ----------------
__device__ __half g_fA[(size_t)NROWS * HQ];        // 128 MB
__device__ __half g_fB[BQ * 3125 * HQ];
__device__ __half g_WT[3 * HQ * 1280];             // [t][n][k] fp16
__device__ int g_perm[65536];
__device__ int g_count[18];
__device__ int g_cursor[18];
__device__ int g_seg[24];

__constant__ int c_n[6]     = {1, 5, 25, 125, 625, 3125};
__constant__ int c_off[6]   = {0, 1, 6, 31, 156, 781};
__constant__ int c_cumM[7]  = {0, 16, 96, 496, 2496, 12496, 62496};
__constant__ int c_pbase[6] = {0, 512, 1024, 2048, 4608, 15104};

// ---------------- helpers ----------------
__device__ __forceinline__ uint32_t smem_u32(const void* p) {
    uint32_t a;
    asm("{ .reg .u64 t; cvta.to.shared.u64 t, %1; cvt.u32.u64 %0, t; }" : "=r"(a) : "l"(p));
    return a;
}
#define SWZ(x) ((x) ^ (((x) >> 3) & 0x70))

#define CP16(d, s)  asm volatile("cp.async.cg.shared.global [%0], [%1], 16;" :: "r"(d), "l"(s) : "memory")
#define CP_COMMIT() asm volatile("cp.async.commit_group;" ::: "memory")
#define CP_WAIT2()  asm volatile("cp.async.wait_group 2;" ::: "memory")
#define CP_WAIT1()  asm volatile("cp.async.wait_group 1;" ::: "memory")
#define CP_WAIT0()  asm volatile("cp.async.wait_group 0;" ::: "memory")

__device__ __forceinline__ void ldm4(uint32_t addr, uint32_t* r) {
    asm volatile("ldmatrix.sync.aligned.m8n8.x4.shared.b16 {%0,%1,%2,%3}, [%4];"
                 : "=r"(r[0]), "=r"(r[1]), "=r"(r[2]), "=r"(r[3]) : "r"(addr));
}
__device__ __forceinline__ void mma16816(float* c, const uint32_t* a, const uint32_t* b) {
    asm volatile(
        "mma.sync.aligned.m16n8k16.row.col.f32.f16.f16.f32 "
        "{%0,%1,%2,%3}, {%4,%5,%6,%7}, {%8,%9}, {%0,%1,%2,%3};"
        : "+f"(c[0]), "+f"(c[1]), "+f"(c[2]), "+f"(c[3])
        : "r"(a[0]), "r"(a[1]), "r"(a[2]), "r"(a[3]), "r"(b[0]), "r"(b[1]));
}

// ---------------- prep kernels (R13-proven) ----------------
__global__ void k_reset() {
    int i = threadIdx.x;
    if (i < 18) { g_count[i] = 0; g_cursor[i] = 0; }
}

__device__ __forceinline__ void decode_row(int r, int& l, int& pr, int& b, int& j) {
    l = 0;
    while (r >= c_cumM[l + 1]) l++;
    pr = r - c_cumM[l];
    int n = c_n[l];
    b = pr / n;
    j = pr - b * n;
}

__global__ void k_count(const int* __restrict__ nt) {
    __shared__ int sc[18];
    int tid = threadIdx.x;
    if (tid < 18) sc[tid] = 0;
    __syncthreads();
    int r = blockIdx.x * blockDim.x + tid;
    if (r < 62496) {
        int l, pr, b, j;
        decode_row(r, l, pr, b, j);
        int t = nt[b * NINT + c_off[l] + j];
        atomicAdd(&sc[l * 3 + t], 1);
    }
    __syncthreads();
    if (tid < 18 && sc[tid]) atomicAdd(&g_count[tid], sc[tid]);
}

__global__ void k_scan() {
    if (threadIdx.x == 0) {
        for (int l = 0; l < 6; l++) {
            int base = 0;
            for (int t = 0; t < 3; t++) {
                g_seg[l * 4 + t] = base;
                base += ((g_count[l * 3 + t] + TMG - 1) / TMG) * TMG;
            }
            g_seg[l * 4 + 3] = base;
        }
    }
}

__global__ void k_scatter(const int* __restrict__ nt) {
    __shared__ int sc[18], sbase[18];
    int tid = threadIdx.x;
    if (tid < 18) sc[tid] = 0;
    __syncthreads();
    int r = blockIdx.x * blockDim.x + tid;
    int lt = -1, lpos = 0, l = 0, pr = 0;
    if (r < 62496) {
        int b, j;
        decode_row(r, l, pr, b, j);
        int t = nt[b * NINT + c_off[l] + j];
        lt = l * 3 + t;
        lpos = atomicAdd(&sc[lt], 1);
    }
    __syncthreads();
    if (tid < 18 && sc[tid]) sbase[tid] = atomicAdd(&g_cursor[tid], sc[tid]);
    __syncthreads();
    if (lt >= 0) {
        int t = lt - l * 3;
        g_perm[c_pbase[l] + g_seg[l * 4 + t] + sbase[lt] + lpos] = pr;
    }
}

// W_node (3,1280,256) -> [t][n][k] fp16, coalesced 32x32 tile transpose
__global__ __launch_bounds__(256) void k_wt(const float* __restrict__ Wn) {
    __shared__ float tile[32][33];
    int bid = blockIdx.x;
    int nb = bid & 7;
    int kb = (bid >> 3) % 40;
    int t  = bid / 320;
    int tx = threadIdx.x & 31;
    int ty = threadIdx.x >> 5;
#pragma unroll
    for (int s = 0; s < 4; s++) {
        int kk = ty + s * 8;
        tile[kk][tx] = Wn[((size_t)t * 1280 + kb * 32 + kk) * HQ + nb * 32 + tx];
    }
    __syncthreads();
#pragma unroll
    for (int s = 0; s < 4; s++) {
        int rr = ty + s * 8;
        g_WT[((size_t)t * HQ + nb * 32 + rr) * 1280 + kb * 32 + tx] =
            __float2half(tile[tx][rr]);
    }
}

// ---------------- leaf encoder (R11-proven) ----------------
__global__ __launch_bounds__(256) void k_leaf(
    const float* __restrict__ lbox, const float* __restrict__ lsem,
    const float* __restrict__ Wb, const float* __restrict__ bb,
    const float* __restrict__ Ws, const float* __restrict__ bs) {
    __shared__ float sbox[64][4];
    __shared__ float ssem[64][16];
    int tid = threadIdx.x;
    long row0 = (long)blockIdx.x * 64;

    {
        long lim = (long)NROWS * 4;
        if (tid < 256) {
            long gi = row0 * 4 + tid;
            sbox[tid >> 2][tid & 3] = (gi < lim) ? lbox[gi] : 0.f;
        }
        long lim2 = (long)NROWS * 16;
#pragma unroll
        for (int i = tid; i < 1024; i += 256) {
            long gi = row0 * 16 + i;
            ssem[i >> 4][i & 15] = (gi < lim2) ? lsem[gi] : 0.f;
        }
    }
    __syncthreads();

    int colgrp = tid & 63;
    int rowgrp = tid >> 6;
    int c = colgrp * 4;

    float4 wb[4], ws[16];
#pragma unroll
    for (int q = 0; q < 4; q++)  wb[q] = *(const float4*)(Wb + q * HQ + c);
#pragma unroll
    for (int q = 0; q < 16; q++) ws[q] = *(const float4*)(Ws + q * HQ + c);
    float4 bbv = *(const float4*)(bb + c);
    float4 bsv = *(const float4*)(bs + c);

#pragma unroll 4
    for (int rr = 0; rr < 16; rr++) {
        int rl = rowgrp * 16 + rr;
        long row = row0 + rl;
        if (row >= NROWS) break;
        float acc[4] = {bbv.x, bbv.y, bbv.z, bbv.w};
#pragma unroll
        for (int q = 0; q < 4; q++) {
            float x = sbox[rl][q];
            acc[0] = fmaf(x, wb[q].x, acc[0]); acc[1] = fmaf(x, wb[q].y, acc[1]);
            acc[2] = fmaf(x, wb[q].z, acc[2]); acc[3] = fmaf(x, wb[q].w, acc[3]);
        }
        float acs[4] = {bsv.x, bsv.y, bsv.z, bsv.w};
#pragma unroll
        for (int q = 0; q < 16; q++) {
            float x = ssem[rl][q];
            acs[0] = fmaf(x, ws[q].x, acs[0]); acs[1] = fmaf(x, ws[q].y, acs[1]);
            acs[2] = fmaf(x, ws[q].z, acs[2]); acs[3] = fmaf(x, ws[q].w, acs[3]);
        }
        float v0 = fmaxf(acc[0], 0.f) + fmaxf(acs[0], 0.f);
        float v1 = fmaxf(acc[1], 0.f) + fmaxf(acs[1], 0.f);
        float v2 = fmaxf(acc[2], 0.f) + fmaxf(acs[2], 0.f);
        float v3 = fmaxf(acc[3], 0.f) + fmaxf(acs[3], 0.f);
        __half2 h0 = __floats2half2_rn(v0, v1);
        __half2 h1 = __floats2half2_rn(v2, v3);
        *(uint2*)(g_fA + row * HQ + c) =
            make_uint2(*(uint32_t*)&h0, *(uint32_t*)&h1);
    }
}

// ---------------- shared helpers ----------------
__device__ __forceinline__ void shared_setup(
    char* smem, int t, int n0, int tid,
    const float* __restrict__ Wb, const float* __restrict__ bb,
    const float* __restrict__ bn) {
    float* s_wbox  = (float*)(smem + 1024);
    float* s_bbox  = (float*)(smem + 3072);
    float* s_bnode = (float*)(smem + 3584);
    if (tid < 128) {
#pragma unroll
        for (int q = 0; q < 4; q++) s_wbox[q * 128 + tid] = Wb[q * HQ + n0 + tid];
        s_bbox[tid] = bb[n0 + tid];
        s_bnode[tid] = bn[t * HQ + n0 + tid];
    }
}

// ---------------- TM=64 GEMM, 2-stage ring, 3 CTA/SM (levels 5 and 4) ----------------
__device__ __forceinline__ void load_stage64(
    uint32_t base, int k0, int t, int n0, int tid,
    const __half* __restrict__ src, const int* __restrict__ s_ab) {
#pragma unroll
    for (int i = 0; i < 2; i++) {
        int it = tid + i * 256;
        int row = (it >> 3) & 63;
        int ch = it & 7;
        const __half* sp = src + (size_t)s_ab[row] + k0 + ch * 8;
        uint32_t off = (uint32_t)(row * 128 + ch * 16);
        CP16(base + SWZ(off), sp);
    }
    const __half* wh = g_WT + (size_t)t * HQ * 1280;
    uint32_t bbase = base + 8192;
#pragma unroll
    for (int i = 0; i < 4; i++) {
        int it = tid + i * 256;
        int row = (it >> 3) & 127;
        int ch = it & 7;
        const __half* sp = wh + (size_t)(n0 + row) * 1280 + k0 + ch * 8;
        uint32_t off = (uint32_t)(row * 128 + ch * 16);
        CP16(bbase + SWZ(off), sp);
    }
}

__global__ __launch_bounds__(256, 3) void k_tc64(
    int srcA, int lvl, int n, int off,
    const float* __restrict__ ibox, const float* __restrict__ bn,
    const float* __restrict__ Wb, const float* __restrict__ bb) {
    extern __shared__ __align__(128) char smem[];
    uint32_t sb = smem_u32(smem);
    int tid = threadIdx.x, wid = tid >> 5, lid = tid & 31;
    int wm = wid & 1, wn = wid >> 1;   // 2 x 4; warp tile 32x32

    int m0 = blockIdx.y * 64;
    int total = g_seg[lvl * 4 + 3];
    if (m0 >= total) return;
    int t = (m0 >= g_seg[lvl * 4 + 2]) ? 2 : (m0 >= g_seg[lvl * 4 + 1]) ? 1 : 0;
    int n0 = blockIdx.x * TNG;

    const __half* src = srcA ? g_fA : g_fB;
    __half* dst = srcA ? g_fB : g_fA;

    int* s_pr = (int*)(smem);
    int* s_ab = (int*)(smem + 512);
    if (tid < 64) {
        int idx = m0 + tid;
        int lim = g_seg[lvl * 4 + t] + g_count[lvl * 3 + t];
        int pr = (idx < lim) ? g_perm[c_pbase[lvl] + idx] : -1;
        s_pr[tid] = pr;
        s_ab[tid] = (pr < 0 ? 0 : pr) * 1280;
    }
    shared_setup(smem, t, n0, tid, Wb, bb, bn);
    __syncthreads();

    load_stage64(sb + 4096, 0, t, n0, tid, src, s_ab);
    CP_COMMIT();

    float acc[2][4][4];
#pragma unroll
    for (int i = 0; i < 2; i++)
#pragma unroll
        for (int j = 0; j < 4; j++)
#pragma unroll
            for (int q = 0; q < 4; q++) acc[i][j][q] = 0.f;

    int a_lrow = lid & 15;
    int a_lcol = (lid >> 4) & 1;
    int b_nrow = (lid & 7) | ((lid >> 1) & 8);
    int b_kcol = (lid >> 3) & 1;

    for (int s = 0; s < NSTAGE; s++) {
        if (s + 1 < NSTAGE) {
            load_stage64(sb + 4096 + ((s + 1) & 1) * STAGE64, (s + 1) * KC, t, n0, tid, src, s_ab);
            CP_COMMIT();
            CP_WAIT1();
        } else {
            CP_WAIT0();
        }
        __syncthreads();

        uint32_t base = sb + 4096 + (s & 1) * STAGE64;
#pragma unroll
        for (int ks = 0; ks < 4; ks++) {
            uint32_t ah[4], bh[4][2];
            {
                uint32_t offA = (uint32_t)((wm * 32 + a_lrow) * 128 + ks * 32 + a_lcol * 16);
                ldm4(base + SWZ(offA), ah);
            }
#pragma unroll
            for (int np = 0; np < 2; np++) {
                uint32_t offB = (uint32_t)((wn * 32 + np * 16 + b_nrow) * 128 + ks * 32 + b_kcol * 16);
                uint32_t r[4];
                ldm4(base + 8192 + SWZ(offB), r);
                bh[2 * np][0] = r[0]; bh[2 * np][1] = r[1];
                bh[2 * np + 1][0] = r[2]; bh[2 * np + 1][1] = r[3];
            }
#pragma unroll
            for (int nt = 0; nt < 4; nt++)
                mma16816(acc[0][nt], ah, bh[nt]);
            {
                uint32_t offA = (uint32_t)((wm * 32 + 16 + a_lrow) * 128 + ks * 32 + a_lcol * 16);
                ldm4(base + SWZ(offA), ah);
            }
#pragma unroll
            for (int nt = 0; nt < 4; nt++)
                mma16816(acc[1][nt], ah, bh[nt]);
        }
        __syncthreads();
    }

    // epilogue: rows wm*32 + mt*16 + ..., cols wn*32 + nt*8 + ...
    int lq = lid >> 2, lr = (lid & 3) * 2;
    float* s_wbox  = (float*)(smem + 1024);
    float* s_bbox  = (float*)(smem + 3072);
    float* s_bnode = (float*)(smem + 3584);
#pragma unroll
    for (int mt = 0; mt < 2; mt++) {
#pragma unroll
        for (int h2 = 0; h2 < 2; h2++) {
            int m = wm * 32 + mt * 16 + lq + h2 * 8;
            int pr = s_pr[m];
            if (pr < 0) continue;
            int b = pr / n, j = pr - b * n;
            float4 bx = *(const float4*)(ibox + ((size_t)b * NINT + off + j) * 4);
#pragma unroll
            for (int nt = 0; nt < 4; nt++) {
                int cl = wn * 32 + nt * 8 + lr;
                float o[2];
#pragma unroll
                for (int u = 0; u < 2; u++) {
                    float be = s_bbox[cl + u];
                    be = fmaf(bx.x, s_wbox[cl + u], be);
                    be = fmaf(bx.y, s_wbox[128 + cl + u], be);
                    be = fmaf(bx.z, s_wbox[256 + cl + u], be);
                    be = fmaf(bx.w, s_wbox[384 + cl + u], be);
                    float v = acc[mt][nt][h2 * 2 + u] + s_bnode[cl + u];
                    o[u] = fmaxf(v, 0.f) + fmaxf(be, 0.f);
                }
                __half2 hv = __floats2half2_rn(o[0], o[1]);
                *(uint32_t*)(dst + (size_t)pr * HQ + n0 + cl) = *(uint32_t*)&hv;
            }
        }
    }
}

// ---------------- TM=32 GEMM (levels 3..0; R12-proven) ----------------
__device__ __forceinline__ void load_stage32(
    uint32_t base, int k0, int t, int n0, int tid,
    const __half* __restrict__ src, const int* __restrict__ s_ab) {
    {
        int row = (tid >> 3) & 31;
        int ch = tid & 7;
        const __half* sp = src + (size_t)s_ab[row] + k0 + ch * 8;
        uint32_t off = (uint32_t)(row * 128 + ch * 16);
        CP16(base + SWZ(off), sp);
    }
    const __half* wh = g_WT + (size_t)t * HQ * 1280;
    uint32_t bbase = base + 4096;
#pragma unroll
    for (int i = 0; i < 4; i++) {
        int it = tid + i * 256;
        int row = (it >> 3) & 127;
        int ch = it & 7;
        const __half* sp = wh + (size_t)(n0 + row) * 1280 + k0 + ch * 8;
        uint32_t off = (uint32_t)(row * 128 + ch * 16);
        CP16(bbase + SWZ(off), sp);
    }
}

__global__ __launch_bounds__(256, 2) void k_tc32(
    int srcA, int lvl, int n, int off,
    const float* __restrict__ ibox, const float* __restrict__ bn,
    const float* __restrict__ Wb, const float* __restrict__ bb) {
    extern __shared__ __align__(128) char smem[];
    uint32_t sb = smem_u32(smem);
    int tid = threadIdx.x, wid = tid >> 5, lid = tid & 31;
    int wn = wid;

    int m0 = blockIdx.y * 32;
    int total = g_seg[lvl * 4 + 3];
    if (m0 >= total) return;
    int t = (m0 >= g_seg[lvl * 4 + 2]) ? 2 : (m0 >= g_seg[lvl * 4 + 1]) ? 1 : 0;
    int n0 = blockIdx.x * TNG;

    const __half* src = srcA ? g_fA : g_fB;
    __half* dst = srcA ? g_fB : g_fA;

    int* s_pr = (int*)(smem);
    int* s_ab = (int*)(smem + 512);
    if (tid < 32) {
        int idx = m0 + tid;
        int lim = g_seg[lvl * 4 + t] + g_count[lvl * 3 + t];
        int pr = (idx < lim) ? g_perm[c_pbase[lvl] + idx] : -1;
        s_pr[tid] = pr;
        s_ab[tid] = (pr < 0 ? 0 : pr) * 1280;
    }
    shared_setup(smem, t, n0, tid, Wb, bb, bn);
    __syncthreads();

    load_stage32(sb + 4096, 0, t, n0, tid, src, s_ab);
    CP_COMMIT();
    load_stage32(sb + 4096 + STAGE32, KC, t, n0, tid, src, s_ab);
    CP_COMMIT();

    float acc[2][2][4];
#pragma unroll
    for (int i = 0; i < 2; i++)
#pragma unroll
        for (int j = 0; j < 2; j++)
#pragma unroll
            for (int q = 0; q < 4; q++) acc[i][j][q] = 0.f;

    int a_lrow = lid & 15;
    int a_lcol = (lid >> 4) & 1;
    int b_nrow = (lid & 7) | ((lid >> 1) & 8);
    int b_kcol = (lid >> 3) & 1;

    int stg = 0;
    for (int s = 0; s < NSTAGE; s++) {
        if (s + 2 < NSTAGE) {
            int ns = stg + 2; if (ns >= 3) ns -= 3;
            load_stage32(sb + 4096 + ns * STAGE32, (s + 2) * KC, t, n0, tid, src, s_ab);
        }
        CP_COMMIT();
        CP_WAIT2();
        __syncthreads();

        uint32_t base = sb + 4096 + stg * STAGE32;
#pragma unroll
        for (int ks = 0; ks < 4; ks++) {
            uint32_t ah[2][4], bh[2][2];
#pragma unroll
            for (int mt = 0; mt < 2; mt++) {
                uint32_t offA = (uint32_t)((mt * 16 + a_lrow) * 128 + ks * 32 + a_lcol * 16);
                ldm4(base + SWZ(offA), ah[mt]);
            }
            {
                uint32_t offB = (uint32_t)((wn * 16 + b_nrow) * 128 + ks * 32 + b_kcol * 16);
                uint32_t r[4];
                ldm4(base + 4096 + SWZ(offB), r);
                bh[0][0] = r[0]; bh[0][1] = r[1];
                bh[1][0] = r[2]; bh[1][1] = r[3];
            }
#pragma unroll
            for (int mt = 0; mt < 2; mt++)
#pragma unroll
                for (int nt = 0; nt < 2; nt++)
                    mma16816(acc[mt][nt], ah[mt], bh[nt]);
        }
        __syncthreads();
        stg++; if (stg >= 3) stg = 0;
    }

    int lq = lid >> 2, lr = (lid & 3) * 2;
    float* s_wbox  = (float*)(smem + 1024);
    float* s_bbox  = (float*)(smem + 3072);
    float* s_bnode = (float*)(smem + 3584);
#pragma unroll
    for (int mt = 0; mt < 2; mt++) {
#pragma unroll
        for (int h2 = 0; h2 < 2; h2++) {
            int m = mt * 16 + lq + h2 * 8;
            int pr = s_pr[m];
            if (pr < 0) continue;
            int b = pr / n, j = pr - b * n;
            float4 bx = *(const float4*)(ibox + ((size_t)b * NINT + off + j) * 4);
#pragma unroll
            for (int nt = 0; nt < 2; nt++) {
                int cl = wn * 16 + nt * 8 + lr;
                float o[2];
#pragma unroll
                for (int u = 0; u < 2; u++) {
                    float be = s_bbox[cl + u];
                    be = fmaf(bx.x, s_wbox[cl + u], be);
                    be = fmaf(bx.y, s_wbox[128 + cl + u], be);
                    be = fmaf(bx.z, s_wbox[256 + cl + u], be);
                    be = fmaf(bx.w, s_wbox[384 + cl + u], be);
                    float v = acc[mt][nt][h2 * 2 + u] + s_bnode[cl + u];
                    o[u] = fmaxf(v, 0.f) + fmaxf(be, 0.f);
                }
                __half2 hv = __floats2half2_rn(o[0], o[1]);
                *(uint32_t*)(dst + (size_t)pr * HQ + n0 + cl) = *(uint32_t*)&hv;
            }
        }
    }
}

// ---------------- VAE head ----------------
__global__ void k_head(const float* __restrict__ eps,
                       const float* __restrict__ W1, const float* __restrict__ b1,
                       const float* __restrict__ Wmu, const float* __restrict__ bmu,
                       const float* __restrict__ Wvar, const float* __restrict__ bvar,
                       float* __restrict__ out) {
    int b = blockIdx.x;
    int h = threadIdx.x;
    __shared__ float sroot[HQ];
    __shared__ float senc[HQ];
    sroot[h] = __half2float(g_fA[b * HQ + h]);
    __syncthreads();
    float a = b1[h];
    for (int k = 0; k < HQ; k++) a = fmaf(sroot[k], W1[k * HQ + h], a);
    senc[h] = fmaxf(a, 0.f);
    __syncthreads();
    float mu = bmu[h], lv = bvar[h];
    for (int k = 0; k < HQ; k++) {
        float e = senc[k];
        mu = fmaf(e, Wmu[k * HQ + h], mu);
        lv = fmaf(e, Wvar[k * HQ + h], lv);
    }
    float stdv = expf(0.5f * lv);
    out[b * 2 * HQ + h] = eps[b * HQ + h] * stdv + mu;
    out[b * 2 * HQ + HQ + h] = 1.f + lv - mu * mu - expf(lv);
}

// ---------------- launch ----------------
extern "C" void kernel_launch(void* const* d_in, const int* in_sizes, int n_in,
                              void* d_out, int out_size) {
    const float* leaf_box     = (const float*)d_in[0];
    const float* leaf_sem     = (const float*)d_in[1];
    const float* internal_box = (const float*)d_in[2];
    const int*   node_type    = (const int*)d_in[3];
    const float* eps          = (const float*)d_in[4];
    const float* W_box        = (const float*)d_in[5];
    const float* b_box        = (const float*)d_in[6];
    const float* W_sem        = (const float*)d_in[7];
    const float* b_sem        = (const float*)d_in[8];
    const float* W_node       = (const float*)d_in[9];
    const float* b_node       = (const float*)d_in[10];
    const float* W1           = (const float*)d_in[11];
    const float* b1           = (const float*)d_in[12];
    const float* Wmu          = (const float*)d_in[13];
    const float* bmu          = (const float*)d_in[14];
    const float* Wvar         = (const float*)d_in[15];
    const float* bvar         = (const float*)d_in[16];
    float* out = (float*)d_out;

    cudaFuncSetAttribute(k_tc64, cudaFuncAttributeMaxDynamicSharedMemorySize, SMEM64B);
    cudaFuncSetAttribute(k_tc32, cudaFuncAttributeMaxDynamicSharedMemorySize, SMEM32);

    k_reset<<<1, 64>>>();
    k_count<<<(62496 + 255) / 256, 256>>>(node_type);
    k_scan<<<1, 32>>>();
    k_scatter<<<(62496 + 255) / 256, 256>>>(node_type);
    k_wt<<<960, 256>>>(W_node);
    k_leaf<<<(NROWS + 63) / 64, 256>>>(leaf_box, leaf_sem, W_box, b_box, W_sem, b_sem);

    // level 5: TM=64, 3 CTA/SM, 2-stage ring (up to 788 m-blocks x 2 n)
    {
        dim3 g5(2, 788);
        k_tc64<<<g5, 256, SMEM64B>>>(1, 5, 3125, 781, internal_box, b_node, W_box, b_box);
    }
    // level 4: TM=64 (up to 328 m-blocks x 2 n)
    {
        dim3 g4(2, 164);
        k_tc64<<<g4, 256, SMEM64B>>>(0, 4, 625, 156, internal_box, b_node, W_box, b_box);
    }
    // small levels: TM=32 (R12-proven)
    struct Lv { int srcA, lvl, n, off, gy; };
    const Lv lv[4] = {
        {1, 3, 125, 31, 76},
        {0, 2,  25,  6, 28},
        {1, 1,   5,  1, 16},
        {0, 0,   1,  0, 16},
    };
    for (int i = 0; i < 4; i++) {
        dim3 grid(2, lv[i].gy);
        k_tc32<<<grid, 256, SMEM32>>>(lv[i].srcA, lv[i].lvl, lv[i].n, lv[i].off,
                                      internal_box, b_node, W_box, b_box);
    }

    k_head<<<BQ, HQ>>>(eps, W1, b1, Wmu, bmu, Wvar, bvar, out);
}

// round 16
// speedup vs baseline: 1.0315x; 1.0032x over previous
#include <cuda_runtime.h>
#include <cuda_fp16.h>
#include <cstdint>

// ---------------- problem constants ----------------
#define BQ 16
#define HQ 256
#define NLEAF 15625
#define NINT 3906
#define NROWS (BQ * NLEAF)
#define TMG 128
#define TNG 128
#define KC 64
#define NSTAGE 20
#define STAGE32 20480              // A 4K | B 16K
#define SMEM32X (4096 + 4 * STAGE32)   // 4-stage ring
#define STAGE64 24576              // A 8K | B 16K
#define SMEM64B (4096 + 2 * STAGE64)   // 2-stage ring, 3 CTA/SM
#define LEAF_BLOCKS ((NROWS + 63) / 64)
#define SCAT_BLOCKS ((62496 + 255) / 256)

// ---------------- static device scratch ----------------
__device__ __half g_fA[(size_t)NROWS * HQ];        // 128 MB
__device__ __half g_fB[BQ * 3125 * HQ];
__device__ __half g_WT[3 * HQ * 1280];             // [t][n][k] fp16
__device__ int g_perm[65536];
__device__ int g_count[18];
__device__ int g_cursor[18];
__device__ int g_seg[24];

__constant__ int c_n[6]     = {1, 5, 25, 125, 625, 3125};
__constant__ int c_off[6]   = {0, 1, 6, 31, 156, 781};
__constant__ int c_cumM[7]  = {0, 16, 96, 496, 2496, 12496, 62496};
__constant__ int c_pbase[6] = {0, 512, 1024, 2048, 4608, 15104};

// ---------------- helpers ----------------
__device__ __forceinline__ uint32_t smem_u32(const void* p) {
    uint32_t a;
    asm("{ .reg .u64 t; cvta.to.shared.u64 t, %1; cvt.u32.u64 %0, t; }" : "=r"(a) : "l"(p));
    return a;
}
#define SWZ(x) ((x) ^ (((x) >> 3) & 0x70))

#define CP16(d, s)  asm volatile("cp.async.cg.shared.global [%0], [%1], 16;" :: "r"(d), "l"(s) : "memory")
#define CP_COMMIT() asm volatile("cp.async.commit_group;" ::: "memory")
#define CP_WAIT3()  asm volatile("cp.async.wait_group 3;" ::: "memory")
#define CP_WAIT1()  asm volatile("cp.async.wait_group 1;" ::: "memory")
#define CP_WAIT0()  asm volatile("cp.async.wait_group 0;" ::: "memory")

__device__ __forceinline__ void ldm4(uint32_t addr, uint32_t* r) {
    asm volatile("ldmatrix.sync.aligned.m8n8.x4.shared.b16 {%0,%1,%2,%3}, [%4];"
                 : "=r"(r[0]), "=r"(r[1]), "=r"(r[2]), "=r"(r[3]) : "r"(addr));
}
__device__ __forceinline__ void mma16816(float* c, const uint32_t* a, const uint32_t* b) {
    asm volatile(
        "mma.sync.aligned.m16n8k16.row.col.f32.f16.f16.f32 "
        "{%0,%1,%2,%3}, {%4,%5,%6,%7}, {%8,%9}, {%0,%1,%2,%3};"
        : "+f"(c[0]), "+f"(c[1]), "+f"(c[2]), "+f"(c[3])
        : "r"(a[0]), "r"(a[1]), "r"(a[2]), "r"(a[3]), "r"(b[0]), "r"(b[1]));
}

// ---------------- prep ----------------
__global__ void k_reset() {
    int i = threadIdx.x;
    if (i < 18) { g_count[i] = 0; g_cursor[i] = 0; }
}

__device__ __forceinline__ void decode_row(int r, int& l, int& pr, int& b, int& j) {
    l = 0;
    while (r >= c_cumM[l + 1]) l++;
    pr = r - c_cumM[l];
    int n = c_n[l];
    b = pr / n;
    j = pr - b * n;
}

// fused: blocks [0,245) count; blocks [245, 245+960) W_node transpose
__global__ __launch_bounds__(256) void k_cw(
    const int* __restrict__ nt, const float* __restrict__ Wn) {
    int tid = threadIdx.x;
    if (blockIdx.x < SCAT_BLOCKS) {
        __shared__ int sc[18];
        if (tid < 18) sc[tid] = 0;
        __syncthreads();
        int r = blockIdx.x * 256 + tid;
        if (r < 62496) {
            int l, pr, b, j;
            decode_row(r, l, pr, b, j);
            int t = nt[b * NINT + c_off[l] + j];
            atomicAdd(&sc[l * 3 + t], 1);
        }
        __syncthreads();
        if (tid < 18 && sc[tid]) atomicAdd(&g_count[tid], sc[tid]);
        return;
    }
    __shared__ float tile[32][33];
    int bid = blockIdx.x - SCAT_BLOCKS;
    int nb = bid & 7;
    int kb = (bid >> 3) % 40;
    int t  = bid / 320;
    int tx = tid & 31;
    int ty = tid >> 5;
#pragma unroll
    for (int s = 0; s < 4; s++) {
        int kk = ty + s * 8;
        tile[kk][tx] = Wn[((size_t)t * 1280 + kb * 32 + kk) * HQ + nb * 32 + tx];
    }
    __syncthreads();
#pragma unroll
    for (int s = 0; s < 4; s++) {
        int rr = ty + s * 8;
        g_WT[((size_t)t * HQ + nb * 32 + rr) * 1280 + kb * 32 + tx] =
            __float2half(tile[tx][rr]);
    }
}

__global__ void k_scan() {
    if (threadIdx.x == 0) {
        for (int l = 0; l < 6; l++) {
            int base = 0;
            for (int t = 0; t < 3; t++) {
                g_seg[l * 4 + t] = base;
                base += ((g_count[l * 3 + t] + TMG - 1) / TMG) * TMG;
            }
            g_seg[l * 4 + 3] = base;
        }
    }
}

// fused: blocks [0, LEAF_BLOCKS) leaf encode; [LEAF_BLOCKS, +245) scatter
__global__ __launch_bounds__(256) void k_leaf(
    const float* __restrict__ lbox, const float* __restrict__ lsem,
    const float* __restrict__ Wb, const float* __restrict__ bb,
    const float* __restrict__ Ws, const float* __restrict__ bs,
    const int* __restrict__ nt) {
    int tid = threadIdx.x;
    if (blockIdx.x >= LEAF_BLOCKS) {
        __shared__ int sc[18], sbase[18];
        if (tid < 18) sc[tid] = 0;
        __syncthreads();
        int r = (blockIdx.x - LEAF_BLOCKS) * 256 + tid;
        int lt = -1, lpos = 0, l = 0, pr = 0;
        if (r < 62496) {
            int b, j;
            decode_row(r, l, pr, b, j);
            int t = nt[b * NINT + c_off[l] + j];
            lt = l * 3 + t;
            lpos = atomicAdd(&sc[lt], 1);
        }
        __syncthreads();
        if (tid < 18 && sc[tid]) sbase[tid] = atomicAdd(&g_cursor[tid], sc[tid]);
        __syncthreads();
        if (lt >= 0) {
            int t = lt - l * 3;
            g_perm[c_pbase[l] + g_seg[l * 4 + t] + sbase[lt] + lpos] = pr;
        }
        return;
    }

    __shared__ float sbox[64][4];
    __shared__ float ssem[64][16];
    long row0 = (long)blockIdx.x * 64;
    {
        long lim = (long)NROWS * 4;
        if (tid < 256) {
            long gi = row0 * 4 + tid;
            sbox[tid >> 2][tid & 3] = (gi < lim) ? lbox[gi] : 0.f;
        }
        long lim2 = (long)NROWS * 16;
#pragma unroll
        for (int i = tid; i < 1024; i += 256) {
            long gi = row0 * 16 + i;
            ssem[i >> 4][i & 15] = (gi < lim2) ? lsem[gi] : 0.f;
        }
    }
    __syncthreads();

    int colgrp = tid & 63;
    int rowgrp = tid >> 6;
    int c = colgrp * 4;

    float4 wb[4], ws[16];
#pragma unroll
    for (int q = 0; q < 4; q++)  wb[q] = *(const float4*)(Wb + q * HQ + c);
#pragma unroll
    for (int q = 0; q < 16; q++) ws[q] = *(const float4*)(Ws + q * HQ + c);
    float4 bbv = *(const float4*)(bb + c);
    float4 bsv = *(const float4*)(bs + c);

#pragma unroll 4
    for (int rr = 0; rr < 16; rr++) {
        int rl = rowgrp * 16 + rr;
        long row = row0 + rl;
        if (row >= NROWS) break;
        float acc[4] = {bbv.x, bbv.y, bbv.z, bbv.w};
#pragma unroll
        for (int q = 0; q < 4; q++) {
            float x = sbox[rl][q];
            acc[0] = fmaf(x, wb[q].x, acc[0]); acc[1] = fmaf(x, wb[q].y, acc[1]);
            acc[2] = fmaf(x, wb[q].z, acc[2]); acc[3] = fmaf(x, wb[q].w, acc[3]);
        }
        float acs[4] = {bsv.x, bsv.y, bsv.z, bsv.w};
#pragma unroll
        for (int q = 0; q < 16; q++) {
            float x = ssem[rl][q];
            acs[0] = fmaf(x, ws[q].x, acs[0]); acs[1] = fmaf(x, ws[q].y, acs[1]);
            acs[2] = fmaf(x, ws[q].z, acs[2]); acs[3] = fmaf(x, ws[q].w, acs[3]);
        }
        float v0 = fmaxf(acc[0], 0.f) + fmaxf(acs[0], 0.f);
        float v1 = fmaxf(acc[1], 0.f) + fmaxf(acs[1], 0.f);
        float v2 = fmaxf(acc[2], 0.f) + fmaxf(acs[2], 0.f);
        float v3 = fmaxf(acc[3], 0.f) + fmaxf(acs[3], 0.f);
        __half2 h0 = __floats2half2_rn(v0, v1);
        __half2 h1 = __floats2half2_rn(v2, v3);
        *(uint2*)(g_fA + row * HQ + c) =
            make_uint2(*(uint32_t*)&h0, *(uint32_t*)&h1);
    }
}

// ---------------- shared helpers ----------------
__device__ __forceinline__ void shared_setup(
    char* smem, int t, int n0, int tid,
    const float* __restrict__ Wb, const float* __restrict__ bb,
    const float* __restrict__ bn) {
    float* s_wbox  = (float*)(smem + 1024);
    float* s_bbox  = (float*)(smem + 3072);
    float* s_bnode = (float*)(smem + 3584);
    if (tid < 128) {
#pragma unroll
        for (int q = 0; q < 4; q++) s_wbox[q * 128 + tid] = Wb[q * HQ + n0 + tid];
        s_bbox[tid] = bb[n0 + tid];
        s_bnode[tid] = bn[t * HQ + n0 + tid];
    }
}

// ---------------- TM=64 GEMM, 2-stage ring, 3 CTA/SM (levels 5/4; R15-proven) ----------------
__device__ __forceinline__ void load_stage64(
    uint32_t base, int k0, int t, int n0, int tid,
    const __half* __restrict__ src, const int* __restrict__ s_ab) {
#pragma unroll
    for (int i = 0; i < 2; i++) {
        int it = tid + i * 256;
        int row = (it >> 3) & 63;
        int ch = it & 7;
        const __half* sp = src + (size_t)s_ab[row] + k0 + ch * 8;
        uint32_t off = (uint32_t)(row * 128 + ch * 16);
        CP16(base + SWZ(off), sp);
    }
    const __half* wh = g_WT + (size_t)t * HQ * 1280;
    uint32_t bbase = base + 8192;
#pragma unroll
    for (int i = 0; i < 4; i++) {
        int it = tid + i * 256;
        int row = (it >> 3) & 127;
        int ch = it & 7;
        const __half* sp = wh + (size_t)(n0 + row) * 1280 + k0 + ch * 8;
        uint32_t off = (uint32_t)(row * 128 + ch * 16);
        CP16(bbase + SWZ(off), sp);
    }
}

__global__ __launch_bounds__(256, 3) void k_tc64(
    int srcA, int lvl, int n, int off,
    const float* __restrict__ ibox, const float* __restrict__ bn,
    const float* __restrict__ Wb, const float* __restrict__ bb) {
    extern __shared__ __align__(128) char smem[];
    uint32_t sb = smem_u32(smem);
    int tid = threadIdx.x, wid = tid >> 5, lid = tid & 31;
    int wm = wid & 1, wn = wid >> 1;

    int m0 = blockIdx.y * 64;
    int total = g_seg[lvl * 4 + 3];
    if (m0 >= total) return;
    int t = (m0 >= g_seg[lvl * 4 + 2]) ? 2 : (m0 >= g_seg[lvl * 4 + 1]) ? 1 : 0;
    int n0 = blockIdx.x * TNG;

    const __half* src = srcA ? g_fA : g_fB;
    __half* dst = srcA ? g_fB : g_fA;

    int* s_pr = (int*)(smem);
    int* s_ab = (int*)(smem + 512);
    if (tid < 64) {
        int idx = m0 + tid;
        int lim = g_seg[lvl * 4 + t] + g_count[lvl * 3 + t];
        int pr = (idx < lim) ? g_perm[c_pbase[lvl] + idx] : -1;
        s_pr[tid] = pr;
        s_ab[tid] = (pr < 0 ? 0 : pr) * 1280;
    }
    shared_setup(smem, t, n0, tid, Wb, bb, bn);
    __syncthreads();

    load_stage64(sb + 4096, 0, t, n0, tid, src, s_ab);
    CP_COMMIT();

    float acc[2][4][4];
#pragma unroll
    for (int i = 0; i < 2; i++)
#pragma unroll
        for (int j = 0; j < 4; j++)
#pragma unroll
            for (int q = 0; q < 4; q++) acc[i][j][q] = 0.f;

    int a_lrow = lid & 15;
    int a_lcol = (lid >> 4) & 1;
    int b_nrow = (lid & 7) | ((lid >> 1) & 8);
    int b_kcol = (lid >> 3) & 1;

    for (int s = 0; s < NSTAGE; s++) {
        if (s + 1 < NSTAGE) {
            load_stage64(sb + 4096 + ((s + 1) & 1) * STAGE64, (s + 1) * KC, t, n0, tid, src, s_ab);
            CP_COMMIT();
            CP_WAIT1();
        } else {
            CP_WAIT0();
        }
        __syncthreads();

        uint32_t base = sb + 4096 + (s & 1) * STAGE64;
#pragma unroll
        for (int ks = 0; ks < 4; ks++) {
            uint32_t ah[4], bh[4][2];
            {
                uint32_t offA = (uint32_t)((wm * 32 + a_lrow) * 128 + ks * 32 + a_lcol * 16);
                ldm4(base + SWZ(offA), ah);
            }
#pragma unroll
            for (int np = 0; np < 2; np++) {
                uint32_t offB = (uint32_t)((wn * 32 + np * 16 + b_nrow) * 128 + ks * 32 + b_kcol * 16);
                uint32_t r[4];
                ldm4(base + 8192 + SWZ(offB), r);
                bh[2 * np][0] = r[0]; bh[2 * np][1] = r[1];
                bh[2 * np + 1][0] = r[2]; bh[2 * np + 1][1] = r[3];
            }
#pragma unroll
            for (int nt = 0; nt < 4; nt++)
                mma16816(acc[0][nt], ah, bh[nt]);
            {
                uint32_t offA = (uint32_t)((wm * 32 + 16 + a_lrow) * 128 + ks * 32 + a_lcol * 16);
                ldm4(base + SWZ(offA), ah);
            }
#pragma unroll
            for (int nt = 0; nt < 4; nt++)
                mma16816(acc[1][nt], ah, bh[nt]);
        }
        __syncthreads();
    }

    int lq = lid >> 2, lr = (lid & 3) * 2;
    float* s_wbox  = (float*)(smem + 1024);
    float* s_bbox  = (float*)(smem + 3072);
    float* s_bnode = (float*)(smem + 3584);
#pragma unroll
    for (int mt = 0; mt < 2; mt++) {
#pragma unroll
        for (int h2 = 0; h2 < 2; h2++) {
            int m = wm * 32 + mt * 16 + lq + h2 * 8;
            int pr = s_pr[m];
            if (pr < 0) continue;
            int b = pr / n, j = pr - b * n;
            float4 bx = *(const float4*)(ibox + ((size_t)b * NINT + off + j) * 4);
#pragma unroll
            for (int nt = 0; nt < 4; nt++) {
                int cl = wn * 32 + nt * 8 + lr;
                float o[2];
#pragma unroll
                for (int u = 0; u < 2; u++) {
                    float be = s_bbox[cl + u];
                    be = fmaf(bx.x, s_wbox[cl + u], be);
                    be = fmaf(bx.y, s_wbox[128 + cl + u], be);
                    be = fmaf(bx.z, s_wbox[256 + cl + u], be);
                    be = fmaf(bx.w, s_wbox[384 + cl + u], be);
                    float v = acc[mt][nt][h2 * 2 + u] + s_bnode[cl + u];
                    o[u] = fmaxf(v, 0.f) + fmaxf(be, 0.f);
                }
                __half2 hv = __floats2half2_rn(o[0], o[1]);
                *(uint32_t*)(dst + (size_t)pr * HQ + n0 + cl) = *(uint32_t*)&hv;
            }
        }
    }
}

// ---------------- TM=32 GEMM (levels 3..0), 4-stage ring ----------------
__device__ __forceinline__ void load_stage32(
    uint32_t base, int k0, int t, int n0, int tid,
    const __half* __restrict__ src, const int* __restrict__ s_ab) {
    {
        int row = (tid >> 3) & 31;
        int ch = tid & 7;
        const __half* sp = src + (size_t)s_ab[row] + k0 + ch * 8;
        uint32_t off = (uint32_t)(row * 128 + ch * 16);
        CP16(base + SWZ(off), sp);
    }
    const __half* wh = g_WT + (size_t)t * HQ * 1280;
    uint32_t bbase = base + 4096;
#pragma unroll
    for (int i = 0; i < 4; i++) {
        int it = tid + i * 256;
        int row = (it >> 3) & 127;
        int ch = it & 7;
        const __half* sp = wh + (size_t)(n0 + row) * 1280 + k0 + ch * 8;
        uint32_t off = (uint32_t)(row * 128 + ch * 16);
        CP16(bbase + SWZ(off), sp);
    }
}

__global__ __launch_bounds__(256, 2) void k_tc32(
    int srcA, int lvl, int n, int off,
    const float* __restrict__ ibox, const float* __restrict__ bn,
    const float* __restrict__ Wb, const float* __restrict__ bb) {
    extern __shared__ __align__(128) char smem[];
    uint32_t sb = smem_u32(smem);
    int tid = threadIdx.x, wid = tid >> 5, lid = tid & 31;
    int wn = wid;

    int m0 = blockIdx.y * 32;
    int total = g_seg[lvl * 4 + 3];
    if (m0 >= total) return;
    int t = (m0 >= g_seg[lvl * 4 + 2]) ? 2 : (m0 >= g_seg[lvl * 4 + 1]) ? 1 : 0;
    int n0 = blockIdx.x * TNG;

    const __half* src = srcA ? g_fA : g_fB;
    __half* dst = srcA ? g_fB : g_fA;

    int* s_pr = (int*)(smem);
    int* s_ab = (int*)(smem + 512);
    if (tid < 32) {
        int idx = m0 + tid;
        int lim = g_seg[lvl * 4 + t] + g_count[lvl * 3 + t];
        int pr = (idx < lim) ? g_perm[c_pbase[lvl] + idx] : -1;
        s_pr[tid] = pr;
        s_ab[tid] = (pr < 0 ? 0 : pr) * 1280;
    }
    shared_setup(smem, t, n0, tid, Wb, bb, bn);
    __syncthreads();

    load_stage32(sb + 4096, 0, t, n0, tid, src, s_ab);
    CP_COMMIT();
    load_stage32(sb + 4096 + STAGE32, KC, t, n0, tid, src, s_ab);
    CP_COMMIT();
    load_stage32(sb + 4096 + 2 * STAGE32, 2 * KC, t, n0, tid, src, s_ab);
    CP_COMMIT();

    float acc[2][2][4];
#pragma unroll
    for (int i = 0; i < 2; i++)
#pragma unroll
        for (int j = 0; j < 2; j++)
#pragma unroll
            for (int q = 0; q < 4; q++) acc[i][j][q] = 0.f;

    int a_lrow = lid & 15;
    int a_lcol = (lid >> 4) & 1;
    int b_nrow = (lid & 7) | ((lid >> 1) & 8);
    int b_kcol = (lid >> 3) & 1;

    for (int s = 0; s < NSTAGE; s++) {
        if (s + 3 < NSTAGE)
            load_stage32(sb + 4096 + ((s + 3) & 3) * STAGE32, (s + 3) * KC, t, n0, tid, src, s_ab);
        CP_COMMIT();
        CP_WAIT3();
        __syncthreads();

        uint32_t base = sb + 4096 + (s & 3) * STAGE32;
#pragma unroll
        for (int ks = 0; ks < 4; ks++) {
            uint32_t ah[2][4], bh[2][2];
#pragma unroll
            for (int mt = 0; mt < 2; mt++) {
                uint32_t offA = (uint32_t)((mt * 16 + a_lrow) * 128 + ks * 32 + a_lcol * 16);
                ldm4(base + SWZ(offA), ah[mt]);
            }
            {
                uint32_t offB = (uint32_t)((wn * 16 + b_nrow) * 128 + ks * 32 + b_kcol * 16);
                uint32_t r[4];
                ldm4(base + 4096 + SWZ(offB), r);
                bh[0][0] = r[0]; bh[0][1] = r[1];
                bh[1][0] = r[2]; bh[1][1] = r[3];
            }
#pragma unroll
            for (int mt = 0; mt < 2; mt++)
#pragma unroll
                for (int nt = 0; nt < 2; nt++)
                    mma16816(acc[mt][nt], ah[mt], bh[nt]);
        }
        __syncthreads();
    }

    int lq = lid >> 2, lr = (lid & 3) * 2;
    float* s_wbox  = (float*)(smem + 1024);
    float* s_bbox  = (float*)(smem + 3072);
    float* s_bnode = (float*)(smem + 3584);
#pragma unroll
    for (int mt = 0; mt < 2; mt++) {
#pragma unroll
        for (int h2 = 0; h2 < 2; h2++) {
            int m = mt * 16 + lq + h2 * 8;
            int pr = s_pr[m];
            if (pr < 0) continue;
            int b = pr / n, j = pr - b * n;
            float4 bx = *(const float4*)(ibox + ((size_t)b * NINT + off + j) * 4);
#pragma unroll
            for (int nt = 0; nt < 2; nt++) {
                int cl = wn * 16 + nt * 8 + lr;
                float o[2];
#pragma unroll
                for (int u = 0; u < 2; u++) {
                    float be = s_bbox[cl + u];
                    be = fmaf(bx.x, s_wbox[cl + u], be);
                    be = fmaf(bx.y, s_wbox[128 + cl + u], be);
                    be = fmaf(bx.z, s_wbox[256 + cl + u], be);
                    be = fmaf(bx.w, s_wbox[384 + cl + u], be);
                    float v = acc[mt][nt][h2 * 2 + u] + s_bnode[cl + u];
                    o[u] = fmaxf(v, 0.f) + fmaxf(be, 0.f);
                }
                __half2 hv = __floats2half2_rn(o[0], o[1]);
                *(uint32_t*)(dst + (size_t)pr * HQ + n0 + cl) = *(uint32_t*)&hv;
            }
        }
    }
}

// ---------------- VAE head ----------------
__global__ void k_head(const float* __restrict__ eps,
                       const float* __restrict__ W1, const float* __restrict__ b1,
                       const float* __restrict__ Wmu, const float* __restrict__ bmu,
                       const float* __restrict__ Wvar, const float* __restrict__ bvar,
                       float* __restrict__ out) {
    int b = blockIdx.x;
    int h = threadIdx.x;
    __shared__ float sroot[HQ];
    __shared__ float senc[HQ];
    sroot[h] = __half2float(g_fA[b * HQ + h]);
    __syncthreads();
    float a = b1[h];
    for (int k = 0; k < HQ; k++) a = fmaf(sroot[k], W1[k * HQ + h], a);
    senc[h] = fmaxf(a, 0.f);
    __syncthreads();
    float mu = bmu[h], lv = bvar[h];
    for (int k = 0; k < HQ; k++) {
        float e = senc[k];
        mu = fmaf(e, Wmu[k * HQ + h], mu);
        lv = fmaf(e, Wvar[k * HQ + h], lv);
    }
    float stdv = expf(0.5f * lv);
    out[b * 2 * HQ + h] = eps[b * HQ + h] * stdv + mu;
    out[b * 2 * HQ + HQ + h] = 1.f + lv - mu * mu - expf(lv);
}

// ---------------- launch ----------------
extern "C" void kernel_launch(void* const* d_in, const int* in_sizes, int n_in,
                              void* d_out, int out_size) {
    const float* leaf_box     = (const float*)d_in[0];
    const float* leaf_sem     = (const float*)d_in[1];
    const float* internal_box = (const float*)d_in[2];
    const int*   node_type    = (const int*)d_in[3];
    const float* eps          = (const float*)d_in[4];
    const float* W_box        = (const float*)d_in[5];
    const float* b_box        = (const float*)d_in[6];
    const float* W_sem        = (const float*)d_in[7];
    const float* b_sem        = (const float*)d_in[8];
    const float* W_node       = (const float*)d_in[9];
    const float* b_node       = (const float*)d_in[10];
    const float* W1           = (const float*)d_in[11];
    const float* b1           = (const float*)d_in[12];
    const float* Wmu          = (const float*)d_in[13];
    const float* bmu          = (const float*)d_in[14];
    const float* Wvar         = (const float*)d_in[15];
    const float* bvar         = (const float*)d_in[16];
    float* out = (float*)d_out;

    cudaFuncSetAttribute(k_tc64, cudaFuncAttributeMaxDynamicSharedMemorySize, SMEM64B);
    cudaFuncSetAttribute(k_tc32, cudaFuncAttributeMaxDynamicSharedMemorySize, SMEM32X);

    k_reset<<<1, 64>>>();
    k_cw<<<SCAT_BLOCKS + 960, 256>>>(node_type, W_node);
    k_scan<<<1, 32>>>();
    k_leaf<<<LEAF_BLOCKS + SCAT_BLOCKS, 256>>>(leaf_box, leaf_sem, W_box, b_box,
                                               W_sem, b_sem, node_type);

    // level 5 / 4: TM=64, 3 CTA/SM, 2-stage ring (R15-proven)
    {
        dim3 g5(2, 788);
        k_tc64<<<g5, 256, SMEM64B>>>(1, 5, 3125, 781, internal_box, b_node, W_box, b_box);
        dim3 g4(2, 164);
        k_tc64<<<g4, 256, SMEM64B>>>(0, 4, 625, 156, internal_box, b_node, W_box, b_box);
    }
    // small levels: TM=32, 4-stage ring
    struct Lv { int srcA, lvl, n, off, gy; };
    const Lv lv[4] = {
        {1, 3, 125, 31, 76},
        {0, 2,  25,  6, 28},
        {1, 1,   5,  1, 16},
        {0, 0,   1,  0, 16},
    };
    for (int i = 0; i < 4; i++) {
        dim3 grid(2, lv[i].gy);
        k_tc32<<<grid, 256, SMEM32X>>>(lv[i].srcA, lv[i].lvl, lv[i].n, lv[i].off,
                                       internal_box, b_node, W_box, b_box);
    }

    k_head<<<BQ, HQ>>>(eps, W1, b1, Wmu, bmu, Wvar, bvar, out);
}

// round 17
// speedup vs baseline: 1.0549x; 1.0227x over previous
#include <cuda_runtime.h>
#include <cuda_fp16.h>
#include <cstdint>

// ---------------- problem constants ----------------
#define BQ 16
#define HQ 256
#define NLEAF 15625
#define NINT 3906
#define NROWS (BQ * NLEAF)
#define TMG 128
#define TNG 128
#define KC 64
#define NSTAGE 20
#define STAGE32 20480              // A 4K | B 16K
#define SMEM32X (4096 + 4 * STAGE32)   // 4-stage ring
#define STAGE64 24576              // A 8K | B 16K
#define SMEM64B (4096 + 2 * STAGE64)   // 2-stage ring, 3 CTA/SM
#define LEAF_BLOCKS ((NROWS + 63) / 64)
#define SCAT_BLOCKS ((62496 + 255) / 256)

// ---------------- static device scratch ----------------
__device__ __half g_fA[(size_t)NROWS * HQ];        // 128 MB
__device__ __half g_fB[BQ * 3125 * HQ];
__device__ __half g_WT[3 * HQ * 1280];             // [t][n][k] fp16
__device__ int g_perm[65536];
__device__ int g_count[18];
__device__ int g_cursor[18];
__device__ int g_seg[24];

__constant__ int c_n[6]     = {1, 5, 25, 125, 625, 3125};
__constant__ int c_off[6]   = {0, 1, 6, 31, 156, 781};
__constant__ int c_cumM[7]  = {0, 16, 96, 496, 2496, 12496, 62496};
__constant__ int c_pbase[6] = {0, 512, 1024, 2048, 4608, 15104};

// ---------------- helpers ----------------
__device__ __forceinline__ uint32_t smem_u32(const void* p) {
    uint32_t a;
    asm("{ .reg .u64 t; cvta.to.shared.u64 t, %1; cvt.u32.u64 %0, t; }" : "=r"(a) : "l"(p));
    return a;
}
#define SWZ(x) ((x) ^ (((x) >> 3) & 0x70))

#define CP16(d, s)  asm volatile("cp.async.cg.shared.global [%0], [%1], 16;" :: "r"(d), "l"(s) : "memory")
#define CP_COMMIT() asm volatile("cp.async.commit_group;" ::: "memory")
#define CP_WAIT3()  asm volatile("cp.async.wait_group 3;" ::: "memory")
#define CP_WAIT1()  asm volatile("cp.async.wait_group 1;" ::: "memory")
#define CP_WAIT0()  asm volatile("cp.async.wait_group 0;" ::: "memory")

__device__ __forceinline__ void ldm4(uint32_t addr, uint32_t* r) {
    asm volatile("ldmatrix.sync.aligned.m8n8.x4.shared.b16 {%0,%1,%2,%3}, [%4];"
                 : "=r"(r[0]), "=r"(r[1]), "=r"(r[2]), "=r"(r[3]) : "r"(addr));
}
__device__ __forceinline__ void mma16816(float* c, const uint32_t* a, const uint32_t* b) {
    asm volatile(
        "mma.sync.aligned.m16n8k16.row.col.f32.f16.f16.f32 "
        "{%0,%1,%2,%3}, {%4,%5,%6,%7}, {%8,%9}, {%0,%1,%2,%3};"
        : "+f"(c[0]), "+f"(c[1]), "+f"(c[2]), "+f"(c[3])
        : "r"(a[0]), "r"(a[1]), "r"(a[2]), "r"(a[3]), "r"(b[0]), "r"(b[1]));
}

// packed fp32x2 FMA: d = a*b + d (per-lane IEEE fma)
__device__ __forceinline__ void fma2(unsigned long long& d,
                                     unsigned long long a, unsigned long long b) {
    asm("fma.rn.f32x2 %0, %1, %2, %0;" : "+l"(d) : "l"(a), "l"(b));
}
__device__ __forceinline__ unsigned long long pack2(float lo, float hi) {
    unsigned long long r;
    asm("mov.b64 %0, {%1, %2};" : "=l"(r) : "f"(lo), "f"(hi));
    return r;
}
__device__ __forceinline__ void unpack2(unsigned long long v, float& lo, float& hi) {
    asm("mov.b64 {%0, %1}, %2;" : "=f"(lo), "=f"(hi) : "l"(v));
}

// ---------------- prep ----------------
__global__ void k_reset() {
    int i = threadIdx.x;
    if (i < 18) { g_count[i] = 0; g_cursor[i] = 0; }
}

__device__ __forceinline__ void decode_row(int r, int& l, int& pr, int& b, int& j) {
    l = 0;
    while (r >= c_cumM[l + 1]) l++;
    pr = r - c_cumM[l];
    int n = c_n[l];
    b = pr / n;
    j = pr - b * n;
}

// fused: blocks [0,245) count; blocks [245, 245+960) W_node transpose
__global__ __launch_bounds__(256) void k_cw(
    const int* __restrict__ nt, const float* __restrict__ Wn) {
    int tid = threadIdx.x;
    if (blockIdx.x < SCAT_BLOCKS) {
        __shared__ int sc[18];
        if (tid < 18) sc[tid] = 0;
        __syncthreads();
        int r = blockIdx.x * 256 + tid;
        if (r < 62496) {
            int l, pr, b, j;
            decode_row(r, l, pr, b, j);
            int t = nt[b * NINT + c_off[l] + j];
            atomicAdd(&sc[l * 3 + t], 1);
        }
        __syncthreads();
        if (tid < 18 && sc[tid]) atomicAdd(&g_count[tid], sc[tid]);
        return;
    }
    __shared__ float tile[32][33];
    int bid = blockIdx.x - SCAT_BLOCKS;
    int nb = bid & 7;
    int kb = (bid >> 3) % 40;
    int t  = bid / 320;
    int tx = tid & 31;
    int ty = tid >> 5;
#pragma unroll
    for (int s = 0; s < 4; s++) {
        int kk = ty + s * 8;
        tile[kk][tx] = Wn[((size_t)t * 1280 + kb * 32 + kk) * HQ + nb * 32 + tx];
    }
    __syncthreads();
#pragma unroll
    for (int s = 0; s < 4; s++) {
        int rr = ty + s * 8;
        g_WT[((size_t)t * HQ + nb * 32 + rr) * 1280 + kb * 32 + tx] =
            __float2half(tile[tx][rr]);
    }
}

__global__ void k_scan() {
    if (threadIdx.x == 0) {
        for (int l = 0; l < 6; l++) {
            int base = 0;
            for (int t = 0; t < 3; t++) {
                g_seg[l * 4 + t] = base;
                base += ((g_count[l * 3 + t] + TMG - 1) / TMG) * TMG;
            }
            g_seg[l * 4 + 3] = base;
        }
    }
}

// fused: blocks [0, LEAF_BLOCKS) leaf encode (f32x2 path); [LEAF_BLOCKS, +245) scatter
__global__ __launch_bounds__(256) void k_leaf(
    const float* __restrict__ lbox, const float* __restrict__ lsem,
    const float* __restrict__ Wb, const float* __restrict__ bb,
    const float* __restrict__ Ws, const float* __restrict__ bs,
    const int* __restrict__ nt) {
    int tid = threadIdx.x;
    if (blockIdx.x >= LEAF_BLOCKS) {
        __shared__ int sc[18], sbase[18];
        if (tid < 18) sc[tid] = 0;
        __syncthreads();
        int r = (blockIdx.x - LEAF_BLOCKS) * 256 + tid;
        int lt = -1, lpos = 0, l = 0, pr = 0;
        if (r < 62496) {
            int b, j;
            decode_row(r, l, pr, b, j);
            int t = nt[b * NINT + c_off[l] + j];
            lt = l * 3 + t;
            lpos = atomicAdd(&sc[lt], 1);
        }
        __syncthreads();
        if (tid < 18 && sc[tid]) sbase[tid] = atomicAdd(&g_cursor[tid], sc[tid]);
        __syncthreads();
        if (lt >= 0) {
            int t = lt - l * 3;
            g_perm[c_pbase[l] + g_seg[l * 4 + t] + sbase[lt] + lpos] = pr;
        }
        return;
    }

    __shared__ float sbox[64][4];
    __shared__ float ssem[64][16];
    long row0 = (long)blockIdx.x * 64;
    {
        long lim = (long)NROWS * 4;
        if (tid < 256) {
            long gi = row0 * 4 + tid;
            sbox[tid >> 2][tid & 3] = (gi < lim) ? lbox[gi] : 0.f;
        }
        long lim2 = (long)NROWS * 16;
#pragma unroll
        for (int i = tid; i < 1024; i += 256) {
            long gi = row0 * 16 + i;
            ssem[i >> 4][i & 15] = (gi < lim2) ? lsem[gi] : 0.f;
        }
    }
    __syncthreads();

    int colgrp = tid & 63;
    int rowgrp = tid >> 6;
    int c = colgrp * 4;

    // packed weights: pairs (c,c+1) and (c+2,c+3)
    unsigned long long wb01[4], wb23[4], ws01[16], ws23[16];
#pragma unroll
    for (int q = 0; q < 4; q++) {
        float4 w = *(const float4*)(Wb + q * HQ + c);
        wb01[q] = pack2(w.x, w.y);
        wb23[q] = pack2(w.z, w.w);
    }
#pragma unroll
    for (int q = 0; q < 16; q++) {
        float4 w = *(const float4*)(Ws + q * HQ + c);
        ws01[q] = pack2(w.x, w.y);
        ws23[q] = pack2(w.z, w.w);
    }
    float4 bbv = *(const float4*)(bb + c);
    float4 bsv = *(const float4*)(bs + c);
    unsigned long long bb01 = pack2(bbv.x, bbv.y), bb23 = pack2(bbv.z, bbv.w);
    unsigned long long bs01 = pack2(bsv.x, bsv.y), bs23 = pack2(bsv.z, bsv.w);

#pragma unroll 4
    for (int rr = 0; rr < 16; rr++) {
        int rl = rowgrp * 16 + rr;
        long row = row0 + rl;
        if (row >= NROWS) break;
        unsigned long long a01 = bb01, a23 = bb23;
#pragma unroll
        for (int q = 0; q < 4; q++) {
            float x = sbox[rl][q];
            unsigned long long xx = pack2(x, x);
            fma2(a01, xx, wb01[q]);
            fma2(a23, xx, wb23[q]);
        }
        unsigned long long s01 = bs01, s23 = bs23;
#pragma unroll
        for (int q = 0; q < 16; q++) {
            float x = ssem[rl][q];
            unsigned long long xx = pack2(x, x);
            fma2(s01, xx, ws01[q]);
            fma2(s23, xx, ws23[q]);
        }
        float a0, a1, a2, a3, e0, e1, e2, e3;
        unpack2(a01, a0, a1); unpack2(a23, a2, a3);
        unpack2(s01, e0, e1); unpack2(s23, e2, e3);
        float v0 = fmaxf(a0, 0.f) + fmaxf(e0, 0.f);
        float v1 = fmaxf(a1, 0.f) + fmaxf(e1, 0.f);
        float v2 = fmaxf(a2, 0.f) + fmaxf(e2, 0.f);
        float v3 = fmaxf(a3, 0.f) + fmaxf(e3, 0.f);
        __half2 h0 = __floats2half2_rn(v0, v1);
        __half2 h1 = __floats2half2_rn(v2, v3);
        *(uint2*)(g_fA + row * HQ + c) =
            make_uint2(*(uint32_t*)&h0, *(uint32_t*)&h1);
    }
}

// ---------------- shared helpers ----------------
__device__ __forceinline__ void shared_setup(
    char* smem, int t, int n0, int tid,
    const float* __restrict__ Wb, const float* __restrict__ bb,
    const float* __restrict__ bn) {
    float* s_wbox  = (float*)(smem + 1024);
    float* s_bbox  = (float*)(smem + 3072);
    float* s_bnode = (float*)(smem + 3584);
    if (tid < 128) {
#pragma unroll
        for (int q = 0; q < 4; q++) s_wbox[q * 128 + tid] = Wb[q * HQ + n0 + tid];
        s_bbox[tid] = bb[n0 + tid];
        s_bnode[tid] = bn[t * HQ + n0 + tid];
    }
}

// ---------------- TM=64 GEMM, 2-stage ring, 3 CTA/SM (levels 5/4; R15-proven) ----------------
__device__ __forceinline__ void load_stage64(
    uint32_t base, int k0, int t, int n0, int tid,
    const __half* __restrict__ src, const int* __restrict__ s_ab) {
#pragma unroll
    for (int i = 0; i < 2; i++) {
        int it = tid + i * 256;
        int row = (it >> 3) & 63;
        int ch = it & 7;
        const __half* sp = src + (size_t)s_ab[row] + k0 + ch * 8;
        uint32_t off = (uint32_t)(row * 128 + ch * 16);
        CP16(base + SWZ(off), sp);
    }
    const __half* wh = g_WT + (size_t)t * HQ * 1280;
    uint32_t bbase = base + 8192;
#pragma unroll
    for (int i = 0; i < 4; i++) {
        int it = tid + i * 256;
        int row = (it >> 3) & 127;
        int ch = it & 7;
        const __half* sp = wh + (size_t)(n0 + row) * 1280 + k0 + ch * 8;
        uint32_t off = (uint32_t)(row * 128 + ch * 16);
        CP16(bbase + SWZ(off), sp);
    }
}

__global__ __launch_bounds__(256, 3) void k_tc64(
    int srcA, int lvl, int n, int off,
    const float* __restrict__ ibox, const float* __restrict__ bn,
    const float* __restrict__ Wb, const float* __restrict__ bb) {
    extern __shared__ __align__(128) char smem[];
    uint32_t sb = smem_u32(smem);
    int tid = threadIdx.x, wid = tid >> 5, lid = tid & 31;
    int wm = wid & 1, wn = wid >> 1;

    int m0 = blockIdx.y * 64;
    int total = g_seg[lvl * 4 + 3];
    if (m0 >= total) return;
    int t = (m0 >= g_seg[lvl * 4 + 2]) ? 2 : (m0 >= g_seg[lvl * 4 + 1]) ? 1 : 0;
    int n0 = blockIdx.x * TNG;

    const __half* src = srcA ? g_fA : g_fB;
    __half* dst = srcA ? g_fB : g_fA;

    int* s_pr = (int*)(smem);
    int* s_ab = (int*)(smem + 512);
    if (tid < 64) {
        int idx = m0 + tid;
        int lim = g_seg[lvl * 4 + t] + g_count[lvl * 3 + t];
        int pr = (idx < lim) ? g_perm[c_pbase[lvl] + idx] : -1;
        s_pr[tid] = pr;
        s_ab[tid] = (pr < 0 ? 0 : pr) * 1280;
    }
    shared_setup(smem, t, n0, tid, Wb, bb, bn);
    __syncthreads();

    load_stage64(sb + 4096, 0, t, n0, tid, src, s_ab);
    CP_COMMIT();

    float acc[2][4][4];
#pragma unroll
    for (int i = 0; i < 2; i++)
#pragma unroll
        for (int j = 0; j < 4; j++)
#pragma unroll
            for (int q = 0; q < 4; q++) acc[i][j][q] = 0.f;

    int a_lrow = lid & 15;
    int a_lcol = (lid >> 4) & 1;
    int b_nrow = (lid & 7) | ((lid >> 1) & 8);
    int b_kcol = (lid >> 3) & 1;

    for (int s = 0; s < NSTAGE; s++) {
        if (s + 1 < NSTAGE) {
            load_stage64(sb + 4096 + ((s + 1) & 1) * STAGE64, (s + 1) * KC, t, n0, tid, src, s_ab);
            CP_COMMIT();
            CP_WAIT1();
        } else {
            CP_WAIT0();
        }
        __syncthreads();

        uint32_t base = sb + 4096 + (s & 1) * STAGE64;
#pragma unroll
        for (int ks = 0; ks < 4; ks++) {
            uint32_t ah[4], bh[4][2];
            {
                uint32_t offA = (uint32_t)((wm * 32 + a_lrow) * 128 + ks * 32 + a_lcol * 16);
                ldm4(base + SWZ(offA), ah);
            }
#pragma unroll
            for (int np = 0; np < 2; np++) {
                uint32_t offB = (uint32_t)((wn * 32 + np * 16 + b_nrow) * 128 + ks * 32 + b_kcol * 16);
                uint32_t r[4];
                ldm4(base + 8192 + SWZ(offB), r);
                bh[2 * np][0] = r[0]; bh[2 * np][1] = r[1];
                bh[2 * np + 1][0] = r[2]; bh[2 * np + 1][1] = r[3];
            }
#pragma unroll
            for (int nt = 0; nt < 4; nt++)
                mma16816(acc[0][nt], ah, bh[nt]);
            {
                uint32_t offA = (uint32_t)((wm * 32 + 16 + a_lrow) * 128 + ks * 32 + a_lcol * 16);
                ldm4(base + SWZ(offA), ah);
            }
#pragma unroll
            for (int nt = 0; nt < 4; nt++)
                mma16816(acc[1][nt], ah, bh[nt]);
        }
        __syncthreads();
    }

    int lq = lid >> 2, lr = (lid & 3) * 2;
    float* s_wbox  = (float*)(smem + 1024);
    float* s_bbox  = (float*)(smem + 3072);
    float* s_bnode = (float*)(smem + 3584);
#pragma unroll
    for (int mt = 0; mt < 2; mt++) {
#pragma unroll
        for (int h2 = 0; h2 < 2; h2++) {
            int m = wm * 32 + mt * 16 + lq + h2 * 8;
            int pr = s_pr[m];
            if (pr < 0) continue;
            int b = pr / n, j = pr - b * n;
            float4 bx = *(const float4*)(ibox + ((size_t)b * NINT + off + j) * 4);
#pragma unroll
            for (int nt = 0; nt < 4; nt++) {
                int cl = wn * 32 + nt * 8 + lr;
                float o[2];
#pragma unroll
                for (int u = 0; u < 2; u++) {
                    float be = s_bbox[cl + u];
                    be = fmaf(bx.x, s_wbox[cl + u], be);
                    be = fmaf(bx.y, s_wbox[128 + cl + u], be);
                    be = fmaf(bx.z, s_wbox[256 + cl + u], be);
                    be = fmaf(bx.w, s_wbox[384 + cl + u], be);
                    float v = acc[mt][nt][h2 * 2 + u] + s_bnode[cl + u];
                    o[u] = fmaxf(v, 0.f) + fmaxf(be, 0.f);
                }
                __half2 hv = __floats2half2_rn(o[0], o[1]);
                *(uint32_t*)(dst + (size_t)pr * HQ + n0 + cl) = *(uint32_t*)&hv;
            }
        }
    }
}

// ---------------- TM=32 GEMM (levels 3..0), 4-stage ring (R16-proven) ----------------
__device__ __forceinline__ void load_stage32(
    uint32_t base, int k0, int t, int n0, int tid,
    const __half* __restrict__ src, const int* __restrict__ s_ab) {
    {
        int row = (tid >> 3) & 31;
        int ch = tid & 7;
        const __half* sp = src + (size_t)s_ab[row] + k0 + ch * 8;
        uint32_t off = (uint32_t)(row * 128 + ch * 16);
        CP16(base + SWZ(off), sp);
    }
    const __half* wh = g_WT + (size_t)t * HQ * 1280;
    uint32_t bbase = base + 4096;
#pragma unroll
    for (int i = 0; i < 4; i++) {
        int it = tid + i * 256;
        int row = (it >> 3) & 127;
        int ch = it & 7;
        const __half* sp = wh + (size_t)(n0 + row) * 1280 + k0 + ch * 8;
        uint32_t off = (uint32_t)(row * 128 + ch * 16);
        CP16(bbase + SWZ(off), sp);
    }
}

__global__ __launch_bounds__(256, 2) void k_tc32(
    int srcA, int lvl, int n, int off,
    const float* __restrict__ ibox, const float* __restrict__ bn,
    const float* __restrict__ Wb, const float* __restrict__ bb) {
    extern __shared__ __align__(128) char smem[];
    uint32_t sb = smem_u32(smem);
    int tid = threadIdx.x, wid = tid >> 5, lid = tid & 31;
    int wn = wid;

    int m0 = blockIdx.y * 32;
    int total = g_seg[lvl * 4 + 3];
    if (m0 >= total) return;
    int t = (m0 >= g_seg[lvl * 4 + 2]) ? 2 : (m0 >= g_seg[lvl * 4 + 1]) ? 1 : 0;
    int n0 = blockIdx.x * TNG;

    const __half* src = srcA ? g_fA : g_fB;
    __half* dst = srcA ? g_fB : g_fA;

    int* s_pr = (int*)(smem);
    int* s_ab = (int*)(smem + 512);
    if (tid < 32) {
        int idx = m0 + tid;
        int lim = g_seg[lvl * 4 + t] + g_count[lvl * 3 + t];
        int pr = (idx < lim) ? g_perm[c_pbase[lvl] + idx] : -1;
        s_pr[tid] = pr;
        s_ab[tid] = (pr < 0 ? 0 : pr) * 1280;
    }
    shared_setup(smem, t, n0, tid, Wb, bb, bn);
    __syncthreads();

    load_stage32(sb + 4096, 0, t, n0, tid, src, s_ab);
    CP_COMMIT();
    load_stage32(sb + 4096 + STAGE32, KC, t, n0, tid, src, s_ab);
    CP_COMMIT();
    load_stage32(sb + 4096 + 2 * STAGE32, 2 * KC, t, n0, tid, src, s_ab);
    CP_COMMIT();

    float acc[2][2][4];
#pragma unroll
    for (int i = 0; i < 2; i++)
#pragma unroll
        for (int j = 0; j < 2; j++)
#pragma unroll
            for (int q = 0; q < 4; q++) acc[i][j][q] = 0.f;

    int a_lrow = lid & 15;
    int a_lcol = (lid >> 4) & 1;
    int b_nrow = (lid & 7) | ((lid >> 1) & 8);
    int b_kcol = (lid >> 3) & 1;

    for (int s = 0; s < NSTAGE; s++) {
        if (s + 3 < NSTAGE)
            load_stage32(sb + 4096 + ((s + 3) & 3) * STAGE32, (s + 3) * KC, t, n0, tid, src, s_ab);
        CP_COMMIT();
        CP_WAIT3();
        __syncthreads();

        uint32_t base = sb + 4096 + (s & 3) * STAGE32;
#pragma unroll
        for (int ks = 0; ks < 4; ks++) {
            uint32_t ah[2][4], bh[2][2];
#pragma unroll
            for (int mt = 0; mt < 2; mt++) {
                uint32_t offA = (uint32_t)((mt * 16 + a_lrow) * 128 + ks * 32 + a_lcol * 16);
                ldm4(base + SWZ(offA), ah[mt]);
            }
            {
                uint32_t offB = (uint32_t)((wn * 16 + b_nrow) * 128 + ks * 32 + b_kcol * 16);
                uint32_t r[4];
                ldm4(base + 4096 + SWZ(offB), r);
                bh[0][0] = r[0]; bh[0][1] = r[1];
                bh[1][0] = r[2]; bh[1][1] = r[3];
            }
#pragma unroll
            for (int mt = 0; mt < 2; mt++)
#pragma unroll
                for (int nt = 0; nt < 2; nt++)
                    mma16816(acc[mt][nt], ah[mt], bh[nt]);
        }
        __syncthreads();
    }

    int lq = lid >> 2, lr = (lid & 3) * 2;
    float* s_wbox  = (float*)(smem + 1024);
    float* s_bbox  = (float*)(smem + 3072);
    float* s_bnode = (float*)(smem + 3584);
#pragma unroll
    for (int mt = 0; mt < 2; mt++) {
#pragma unroll
        for (int h2 = 0; h2 < 2; h2++) {
            int m = mt * 16 + lq + h2 * 8;
            int pr = s_pr[m];
            if (pr < 0) continue;
            int b = pr / n, j = pr - b * n;
            float4 bx = *(const float4*)(ibox + ((size_t)b * NINT + off + j) * 4);
#pragma unroll
            for (int nt = 0; nt < 2; nt++) {
                int cl = wn * 16 + nt * 8 + lr;
                float o[2];
#pragma unroll
                for (int u = 0; u < 2; u++) {
                    float be = s_bbox[cl + u];
                    be = fmaf(bx.x, s_wbox[cl + u], be);
                    be = fmaf(bx.y, s_wbox[128 + cl + u], be);
                    be = fmaf(bx.z, s_wbox[256 + cl + u], be);
                    be = fmaf(bx.w, s_wbox[384 + cl + u], be);
                    float v = acc[mt][nt][h2 * 2 + u] + s_bnode[cl + u];
                    o[u] = fmaxf(v, 0.f) + fmaxf(be, 0.f);
                }
                __half2 hv = __floats2half2_rn(o[0], o[1]);
                *(uint32_t*)(dst + (size_t)pr * HQ + n0 + cl) = *(uint32_t*)&hv;
            }
        }
    }
}

// ---------------- VAE head ----------------
__global__ void k_head(const float* __restrict__ eps,
                       const float* __restrict__ W1, const float* __restrict__ b1,
                       const float* __restrict__ Wmu, const float* __restrict__ bmu,
                       const float* __restrict__ Wvar, const float* __restrict__ bvar,
                       float* __restrict__ out) {
    int b = blockIdx.x;
    int h = threadIdx.x;
    __shared__ float sroot[HQ];
    __shared__ float senc[HQ];
    sroot[h] = __half2float(g_fA[b * HQ + h]);
    __syncthreads();
    float a = b1[h];
    for (int k = 0; k < HQ; k++) a = fmaf(sroot[k], W1[k * HQ + h], a);
    senc[h] = fmaxf(a, 0.f);
    __syncthreads();
    float mu = bmu[h], lv = bvar[h];
    for (int k = 0; k < HQ; k++) {
        float e = senc[k];
        mu = fmaf(e, Wmu[k * HQ + h], mu);
        lv = fmaf(e, Wvar[k * HQ + h], lv);
    }
    float stdv = expf(0.5f * lv);
    out[b * 2 * HQ + h] = eps[b * HQ + h] * stdv + mu;
    out[b * 2 * HQ + HQ + h] = 1.f + lv - mu * mu - expf(lv);
}

// ---------------- launch ----------------
extern "C" void kernel_launch(void* const* d_in, const int* in_sizes, int n_in,
                              void* d_out, int out_size) {
    const float* leaf_box     = (const float*)d_in[0];
    const float* leaf_sem     = (const float*)d_in[1];
    const float* internal_box = (const float*)d_in[2];
    const int*   node_type    = (const int*)d_in[3];
    const float* eps          = (const float*)d_in[4];
    const float* W_box        = (const float*)d_in[5];
    const float* b_box        = (const float*)d_in[6];
    const float* W_sem        = (const float*)d_in[7];
    const float* b_sem        = (const float*)d_in[8];
    const float* W_node       = (const float*)d_in[9];
    const float* b_node       = (const float*)d_in[10];
    const float* W1           = (const float*)d_in[11];
    const float* b1           = (const float*)d_in[12];
    const float* Wmu          = (const float*)d_in[13];
    const float* bmu          = (const float*)d_in[14];
    const float* Wvar         = (const float*)d_in[15];
    const float* bvar         = (const float*)d_in[16];
    float* out = (float*)d_out;

    cudaFuncSetAttribute(k_tc64, cudaFuncAttributeMaxDynamicSharedMemorySize, SMEM64B);
    cudaFuncSetAttribute(k_tc32, cudaFuncAttributeMaxDynamicSharedMemorySize, SMEM32X);

    k_reset<<<1, 64>>>();
    k_cw<<<SCAT_BLOCKS + 960, 256>>>(node_type, W_node);
    k_scan<<<1, 32>>>();
    k_leaf<<<LEAF_BLOCKS + SCAT_BLOCKS, 256>>>(leaf_box, leaf_sem, W_box, b_box,
                                               W_sem, b_sem, node_type);

    // level 5 / 4: TM=64, 3 CTA/SM, 2-stage ring (R15-proven)
    {
        dim3 g5(2, 788);
        k_tc64<<<g5, 256, SMEM64B>>>(1, 5, 3125, 781, internal_box, b_node, W_box, b_box);
        dim3 g4(2, 164);
        k_tc64<<<g4, 256, SMEM64B>>>(0, 4, 625, 156, internal_box, b_node, W_box, b_box);
    }
    // small levels: TM=32, 4-stage ring
    struct Lv { int srcA, lvl, n, off, gy; };
    const Lv lv[4] = {
        {1, 3, 125, 31, 76},
        {0, 2,  25,  6, 28},
        {1, 1,   5,  1, 16},
        {0, 0,   1,  0, 16},
    };
    for (int i = 0; i < 4; i++) {
        dim3 grid(2, lv[i].gy);
        k_tc32<<<grid, 256, SMEM32X>>>(lv[i].srcA, lv[i].lvl, lv[i].n, lv[i].off,
                                       internal_box, b_node, W_box, b_box);
    }

    k_head<<<BQ, HQ>>>(eps, W1, b1, Wmu, bmu, Wvar, bvar, out);
}